// round 3
// baseline (speedup 1.0000x reference)
#include <cuda_runtime.h>

#define BATCHN 8
#define SEQ    2048
#define DIM    1024
#define NS     16
#define ROWS   (BATCHN*SEQ)     // 16384
#define LCH    64               // chunk length
#define CPB    (SEQ/LCH)        // 32 chunks per batch
#define NCHUNK (BATCHN*CPB)     // 256 chunks

// ---------------- scratch (static device globals; no runtime alloc) ----------------
__device__ __align__(128) float g_A[NS*NS];
__device__ float g_Anorm;
__device__ __align__(128) float g_delta[ROWS];
__device__ __align__(128) float g_Bu[ROWS*NS];
__device__ __align__(128) float g_AexpT[(size_t)ROWS*NS*NS];   // 16 MB, E^T per row: [r][m][n] = E[n][m]
__device__ __align__(128) float g_PT[NCHUNK*NS*NS];            // chunk product transposed
__device__ __align__(128) float g_e[NCHUNK*NS];                // chunk local end-state
__device__ __align__(128) float g_hstart[NCHUNK*NS];           // state at chunk start
__device__ __align__(128) float g_hs[(size_t)ROWS*NS];

// ---------------- kernel 0: A = -exp(A_log), inf-norm ----------------
__global__ __launch_bounds__(256) void k_prepA(const float* __restrict__ A_log) {
    __shared__ float As[NS*NS];
    __shared__ float rowsum[NS];
    int tid = threadIdx.x;
    if (tid < NS*NS) {
        float a = -expf(A_log[tid]);
        g_A[tid] = a;
        As[tid] = a;
    }
    __syncthreads();
    if (tid < NS) {
        float s = 0.f;
        #pragma unroll
        for (int j = 0; j < NS; j++) s += fabsf(As[tid*NS + j]);
        rowsum[tid] = s;
    }
    __syncthreads();
    if (tid == 0) {
        float m = 0.f;
        #pragma unroll
        for (int i = 0; i < NS; i++) m = fmaxf(m, rowsum[i]);
        g_Anorm = m;
    }
}

// ---------------- kernel 1a: delta = sigmoid(gate . dt_w + dt_b), warp per row ----------------
__global__ __launch_bounds__(256) void k_delta(const float* __restrict__ gate,
                                               const float* __restrict__ dt_w,
                                               const float* __restrict__ dt_b) {
    int warp = (blockIdx.x * blockDim.x + threadIdx.x) >> 5;
    int lane = threadIdx.x & 31;
    if (warp >= ROWS) return;
    const float4* g4 = (const float4*)(gate + (size_t)warp * DIM);
    const float4* w4 = (const float4*)dt_w;
    float acc = 0.f;
    #pragma unroll
    for (int i = 0; i < 8; i++) {
        float4 g = g4[lane + 32*i];
        float4 w = w4[lane + 32*i];
        acc += g.x*w.x + g.y*w.y + g.z*w.z + g.w*w.w;
    }
    #pragma unroll
    for (int o = 16; o; o >>= 1) acc += __shfl_xor_sync(0xffffffffu, acc, o);
    if (lane == 0) g_delta[warp] = 1.f / (1.f + expf(-(acc + dt_b[0])));
}

// ---------------- kernel 1b: Bu = u @ B_mat, block = 16 rows x 16 states ----------------
__global__ __launch_bounds__(256) void k_bu(const float* __restrict__ u,
                                            const float* __restrict__ B) {
    __shared__ float us[16][133];
    __shared__ float Bs[128][NS];
    int tid = threadIdx.x;
    int r0 = blockIdx.x * 16;
    int n = tid >> 4, sl = tid & 15;
    float acc0 = 0.f, acc1 = 0.f, acc2 = 0.f, acc3 = 0.f;
    for (int dt = 0; dt < DIM; dt += 128) {
        #pragma unroll
        for (int it = 0; it < 8; it++) {
            int idx = tid + it * 256;           // 0..2047
            us[idx >> 7][idx & 127] = u[(size_t)(r0 + (idx >> 7)) * DIM + dt + (idx & 127)];
            Bs[idx >> 4][idx & 15]  = B[(size_t)(dt + (idx >> 4)) * NS + (idx & 15)];
        }
        __syncthreads();
        #pragma unroll
        for (int dd = 0; dd < 128; dd += 4) {
            acc0 += us[sl][dd+0] * Bs[dd+0][n];
            acc1 += us[sl][dd+1] * Bs[dd+1][n];
            acc2 += us[sl][dd+2] * Bs[dd+2][n];
            acc3 += us[sl][dd+3] * Bs[dd+3][n];
        }
        __syncthreads();
    }
    g_Bu[(size_t)(r0 + sl) * NS + n] = (acc0 + acc1) + (acc2 + acc3);
}

// ---------------- kernel 2: E = expm(delta*A) via scaling-and-squaring, block per row ----------------
__global__ __launch_bounds__(256) void k_expm() {
    __shared__ float Ys[NS*17];
    __shared__ float Ts[NS*17];
    int r = blockIdx.x;
    int tid = threadIdx.x;
    int i = tid >> 4, j = tid & 15;
    float delta = g_delta[r];
    float norm  = delta * g_Anorm;
    int s = 0; float nn = norm;
    while (nn > 0.35f) { nn *= 0.5f; s++; }     // block-uniform (delta uniform per block)
    float y = g_A[tid] * ldexpf(delta, -s);
    Ys[i*17 + j] = y;
    // Horner for Taylor m=9: p = I + Y/9, then 8 iterations p = I + (Y p)/k
    Ts[i*17 + j] = ((i == j) ? 1.f : 0.f) + y * (1.f/9.f);
    __syncthreads();
    #pragma unroll
    for (int k = 8; k >= 1; k--) {
        float val = 0.f;
        #pragma unroll
        for (int kk = 0; kk < NS; kk++) val += Ys[i*17 + kk] * Ts[kk*17 + j];
        __syncthreads();
        Ts[i*17 + j] = ((i == j) ? 1.f : 0.f) + val * (1.f / (float)k);
        __syncthreads();
    }
    for (int q = 0; q < s; q++) {
        float val = 0.f;
        #pragma unroll
        for (int kk = 0; kk < NS; kk++) val += Ts[i*17 + kk] * Ts[kk*17 + j];
        __syncthreads();
        Ts[i*17 + j] = val;
        __syncthreads();
    }
    // store transposed: out[m*16+n] = E[n][m] = Ts[n][m]
    g_AexpT[(size_t)r * 256 + tid] = Ts[(tid & 15)*17 + (tid >> 4)];
}

// ---------------- kernel 3a: per-chunk cumulative matrix P and local end-state e ----------------
__global__ __launch_bounds__(256) void k_chunk() {
    __shared__ float Ps[NS*17];
    __shared__ float Es[NS*17];
    __shared__ float es[NS];
    int gc = blockIdx.x;
    int tid = threadIdx.x;
    int i = tid >> 4, j = tid & 15;
    int r0 = gc * LCH;
    Ps[i*17 + j] = (i == j) ? 1.f : 0.f;
    if (tid < NS) es[tid] = 0.f;
    float cur    = g_AexpT[(size_t)r0 * 256 + tid];
    float bu_cur = (i == 0) ? g_Bu[(size_t)r0 * NS + j] : 0.f;
    __syncthreads();
    for (int t = 0; t < LCH; t++) {
        Es[i*17 + j] = cur;                       // Es[m][n] = E^T[m][n]
        __syncthreads();
        if (t + 1 < LCH) cur = g_AexpT[(size_t)(r0 + t + 1) * 256 + tid];
        float bu_next = (i == 0 && t + 1 < LCH) ? g_Bu[(size_t)(r0 + t + 1) * NS + j] : 0.f;
        // P' = P @ E_t : P'[i][j] = sum_k P[i][k] * E[k][j],  E[k][j] = Es[j][k]
        float val = 0.f;
        #pragma unroll
        for (int k = 0; k < NS; k++) val += Ps[i*17 + k] * Es[j*17 + k];
        float ev = 0.f;
        if (i == 0) {
            ev = bu_cur;
            #pragma unroll
            for (int k = 0; k < NS; k++) ev += es[k] * Es[j*17 + k];
        }
        __syncthreads();
        Ps[i*17 + j] = val;
        if (i == 0) es[j] = ev;
        bu_cur = bu_next;
        __syncthreads();
    }
    g_PT[gc * 256 + tid] = Ps[(tid & 15)*17 + (tid >> 4)];   // PT[m][n] = P[n][m]
    if (tid < NS) g_e[gc * NS + tid] = es[tid];
}

// ---------------- kernel 3b: sequential chunk combine, warp per batch ----------------
__global__ __launch_bounds__(256) void k_combine() {
    int tid  = threadIdx.x;
    int b    = tid >> 5;
    int lane = tid & 31;
    int m    = lane & 15;
    float h = 0.f;
    for (int c = 0; c < CPB; c++) {
        int gc = b * CPB + c;
        if (lane < NS) g_hstart[gc * NS + lane] = h;
        const float4* p4 = (const float4*)(g_PT + gc * 256 + m * NS);
        float4 p0 = p4[0], p1 = p4[1], p2 = p4[2], p3 = p4[3];
        float acc = g_e[gc * NS + m];
        float hv[NS];
        #pragma unroll
        for (int n = 0; n < NS; n++) hv[n] = __shfl_sync(0xffffffffu, h, n, 32);
        acc += hv[0]*p0.x + hv[1]*p0.y + hv[2]*p0.z + hv[3]*p0.w
             + hv[4]*p1.x + hv[5]*p1.y + hv[6]*p1.z + hv[7]*p1.w
             + hv[8]*p2.x + hv[9]*p2.y + hv[10]*p2.z + hv[11]*p2.w
             + hv[12]*p3.x + hv[13]*p3.y + hv[14]*p3.z + hv[15]*p3.w;
        h = acc;
    }
}

// ---------------- kernel 3c: per-chunk matvec scan with known start state ----------------
__global__ __launch_bounds__(32) void k_scan() {
    int gc   = blockIdx.x;
    int lane = threadIdx.x & 31;
    int m    = lane & 15;
    int r0   = gc * LCH;
    float h = g_hstart[gc * NS + m];
    const float4* e4 = (const float4*)(g_AexpT + (size_t)r0 * 256 + m * NS);
    float4 a0 = e4[0], a1 = e4[1], a2 = e4[2], a3 = e4[3];
    float bu = g_Bu[(size_t)r0 * NS + m];
    for (int t = 0; t < LCH; t++) {
        float4 b0, b1, b2, b3; float bun = 0.f;
        if (t + 1 < LCH) {
            const float4* n4 = e4 + (size_t)(t + 1) * 64;
            b0 = n4[0]; b1 = n4[1]; b2 = n4[2]; b3 = n4[3];
            bun = g_Bu[(size_t)(r0 + t + 1) * NS + m];
        }
        float hv[NS];
        #pragma unroll
        for (int n = 0; n < NS; n++) hv[n] = __shfl_sync(0xffffffffu, h, n, 32);
        float acc = bu
            + hv[0]*a0.x + hv[1]*a0.y + hv[2]*a0.z + hv[3]*a0.w
            + hv[4]*a1.x + hv[5]*a1.y + hv[6]*a1.z + hv[7]*a1.w
            + hv[8]*a2.x + hv[9]*a2.y + hv[10]*a2.z + hv[11]*a2.w
            + hv[12]*a3.x + hv[13]*a3.y + hv[14]*a3.z + hv[15]*a3.w;
        h = acc;
        if (lane < NS) g_hs[(size_t)(r0 + t) * NS + m] = h;
        a0 = b0; a1 = b1; a2 = b2; a3 = b3; bu = bun;
    }
}

// ---------------- kernel 4: y = hs @ C^T + D*u ----------------
__global__ __launch_bounds__(256) void k_out(const float* __restrict__ u,
                                             const float* __restrict__ C,
                                             const float* __restrict__ D,
                                             float* __restrict__ y) {
    __shared__ float hs_s[16][NS];
    int tid = threadIdx.x;
    int d   = blockIdx.x * 256 + tid;
    int r0  = blockIdx.y * 16;
    hs_s[tid >> 4][tid & 15] = g_hs[(size_t)r0 * NS + tid];
    const float4* c4 = (const float4*)(C + (size_t)d * NS);
    float4 c0 = c4[0], c1 = c4[1], c2 = c4[2], c3 = c4[3];
    float Dd = D[d];
    __syncthreads();
    #pragma unroll 4
    for (int sl = 0; sl < 16; sl++) {
        size_t off = (size_t)(r0 + sl) * DIM + d;
        float yv = Dd * u[off];
        yv += hs_s[sl][0]*c0.x + hs_s[sl][1]*c0.y + hs_s[sl][2]*c0.z + hs_s[sl][3]*c0.w
            + hs_s[sl][4]*c1.x + hs_s[sl][5]*c1.y + hs_s[sl][6]*c1.z + hs_s[sl][7]*c1.w
            + hs_s[sl][8]*c2.x + hs_s[sl][9]*c2.y + hs_s[sl][10]*c2.z + hs_s[sl][11]*c2.w
            + hs_s[sl][12]*c3.x + hs_s[sl][13]*c3.y + hs_s[sl][14]*c3.z + hs_s[sl][15]*c3.w;
        y[off] = yv;
    }
}

// ---------------- launch ----------------
extern "C" void kernel_launch(void* const* d_in, const int* in_sizes, int n_in,
                              void* d_out, int out_size) {
    const float* u     = (const float*)d_in[0];
    const float* gate  = (const float*)d_in[1];
    const float* A_log = (const float*)d_in[2];
    const float* B_mat = (const float*)d_in[3];
    const float* C_mat = (const float*)d_in[4];
    const float* D     = (const float*)d_in[5];
    const float* dt_w  = (const float*)d_in[6];
    const float* dt_b  = (const float*)d_in[7];
    float* y = (float*)d_out;

    k_prepA<<<1, 256>>>(A_log);
    k_delta<<<ROWS/8, 256>>>(gate, dt_w, dt_b);
    k_bu<<<ROWS/16, 256>>>(u, B_mat);
    k_expm<<<ROWS, 256>>>();
    k_chunk<<<NCHUNK, 256>>>();
    k_combine<<<1, 256>>>();
    k_scan<<<NCHUNK, 32>>>();
    k_out<<<dim3(DIM/256, ROWS/16), 256>>>(u, C_mat, D, y);
}

// round 4
// speedup vs baseline: 1.7173x; 1.7173x over previous
#include <cuda_runtime.h>

#define BATCHN 8
#define SEQ    2048
#define DIM    1024
#define NS     16
#define ROWS   (BATCHN*SEQ)     // 16384
#define LCH    64               // chunk length
#define CPB    (SEQ/LCH)        // 32 chunks per batch
#define NCHUNK (BATCHN*CPB)     // 256 chunks
#define NTERMS 13               // Taylor degree 12
#define THETA  2.5f

// ---------------- scratch (static device globals; no runtime alloc) ----------------
__device__ float g_Anorm;
__device__ __align__(128) float g_Pd[NTERMS*256];              // A^k / k!
__device__ __align__(128) float g_delta[ROWS];
__device__ __align__(128) float g_Bu[ROWS*NS];
__device__ __align__(128) float g_AexpT[(size_t)ROWS*NS*NS];   // 16 MB, E^T per row: [r][m][n] = E[n][m]
__device__ __align__(128) float g_PT[NCHUNK*NS*NS];            // chunk product transposed
__device__ __align__(128) float g_e[NCHUNK*NS];                // chunk local end-state
__device__ __align__(128) float g_hstart[NCHUNK*NS];           // state at chunk start
__device__ __align__(128) float g_hs[(size_t)ROWS*NS];

// ---------------- kernel 0: A = -exp(A_log), inf-norm, P_k = A^k/k! ----------------
__global__ __launch_bounds__(256) void k_prepA(const float* __restrict__ A_log) {
    __shared__ float As[256];
    __shared__ float cur[256];
    __shared__ float rowsum[NS];
    int tid = threadIdx.x;
    int i = tid >> 4, j = tid & 15;
    float a = -expf(A_log[tid]);
    As[tid] = a;
    __syncthreads();
    if (tid < NS) {
        float s = 0.f;
        #pragma unroll
        for (int c = 0; c < NS; c++) s += fabsf(As[tid*NS + c]);
        rowsum[tid] = s;
    }
    __syncthreads();
    if (tid == 0) {
        float m = 0.f;
        #pragma unroll
        for (int r = 0; r < NS; r++) m = fmaxf(m, rowsum[r]);
        g_Anorm = m;
    }
    float id = (i == j) ? 1.f : 0.f;
    cur[tid] = id;
    g_Pd[tid] = id;
    __syncthreads();
    for (int k = 1; k < NTERMS; k++) {
        float acc = 0.f;
        #pragma unroll
        for (int kk = 0; kk < NS; kk++) acc += cur[i*NS + kk] * As[kk*NS + j];
        acc *= (1.f / (float)k);
        __syncthreads();
        cur[tid] = acc;
        g_Pd[k*256 + tid] = acc;
        __syncthreads();
    }
}

// ---------------- kernel 1a: delta = sigmoid(gate . dt_w + dt_b), warp per row ----------------
__global__ __launch_bounds__(256) void k_delta(const float* __restrict__ gate,
                                               const float* __restrict__ dt_w,
                                               const float* __restrict__ dt_b) {
    int warp = (blockIdx.x * blockDim.x + threadIdx.x) >> 5;
    int lane = threadIdx.x & 31;
    if (warp >= ROWS) return;
    const float4* g4 = (const float4*)(gate + (size_t)warp * DIM);
    const float4* w4 = (const float4*)dt_w;
    float acc = 0.f;
    #pragma unroll
    for (int i = 0; i < 8; i++) {
        float4 g = g4[lane + 32*i];
        float4 w = w4[lane + 32*i];
        acc += g.x*w.x + g.y*w.y + g.z*w.z + g.w*w.w;
    }
    #pragma unroll
    for (int o = 16; o; o >>= 1) acc += __shfl_xor_sync(0xffffffffu, acc, o);
    if (lane == 0) g_delta[warp] = 1.f / (1.f + expf(-(acc + dt_b[0])));
}

// ---------------- kernel 1b: Bu = u @ B_mat, block = 16 rows x 16 states ----------------
__global__ __launch_bounds__(256) void k_bu(const float* __restrict__ u,
                                            const float* __restrict__ B) {
    __shared__ float us[16][133];
    __shared__ float Bs[128][NS];
    int tid = threadIdx.x;
    int r0 = blockIdx.x * 16;
    int n = tid >> 4, sl = tid & 15;
    float acc0 = 0.f, acc1 = 0.f, acc2 = 0.f, acc3 = 0.f;
    for (int dt = 0; dt < DIM; dt += 128) {
        #pragma unroll
        for (int it = 0; it < 8; it++) {
            int idx = tid + it * 256;           // 0..2047
            us[idx >> 7][idx & 127] = u[(size_t)(r0 + (idx >> 7)) * DIM + dt + (idx & 127)];
            Bs[idx >> 4][idx & 15]  = B[(size_t)(dt + (idx >> 4)) * NS + (idx & 15)];
        }
        __syncthreads();
        #pragma unroll
        for (int dd = 0; dd < 128; dd += 4) {
            acc0 += us[sl][dd+0] * Bs[dd+0][n];
            acc1 += us[sl][dd+1] * Bs[dd+1][n];
            acc2 += us[sl][dd+2] * Bs[dd+2][n];
            acc3 += us[sl][dd+3] * Bs[dd+3][n];
        }
        __syncthreads();
    }
    g_Bu[(size_t)(r0 + sl) * NS + n] = (acc0 + acc1) + (acc2 + acc3);
}

// ---------------- kernel 2: E = expm(delta*A); Taylor-12 via precomputed A^k/k! ----------------
// Block handles 16 rows. Phase A: elementwise Horner in y = delta/2^s (no matmuls).
// Phase B: s squarings via register/shuffle 16x16 matmuls (2 matrices per warp).
__global__ __launch_bounds__(256) void k_expm() {
    __shared__ float Pd[NTERMS*256];
    __shared__ float Ts[16*257];
    __shared__ float ys[16];
    __shared__ int   ss[16];
    int tid = threadIdx.x;
    int r0 = blockIdx.x * 16;
    #pragma unroll
    for (int k = 0; k < NTERMS; k++) Pd[k*256 + tid] = g_Pd[k*256 + tid];
    if (tid < 16) {
        float d = g_delta[r0 + tid];
        float nn = d * g_Anorm;
        int s = 0;
        while (nn > THETA) { nn *= 0.5f; s++; }
        ss[tid] = s;
        ys[tid] = ldexpf(d, -s);
    }
    __syncthreads();
    float p[NTERMS];
    #pragma unroll
    for (int k = 0; k < NTERMS; k++) p[k] = Pd[k*256 + tid];
    #pragma unroll
    for (int r = 0; r < 16; r++) {
        float y = ys[r];
        float acc = p[NTERMS-1];
        #pragma unroll
        for (int k = NTERMS-2; k >= 0; k--) acc = acc*y + p[k];
        Ts[r*257 + tid] = acc;
    }
    __syncthreads();
    int r = tid >> 4, j = tid & 15;
    float v[16];
    #pragma unroll
    for (int i = 0; i < 16; i++) v[i] = Ts[r*257 + i*16 + j];   // v = T[:,j] of row r
    int s = ss[r];
    int smax = max(s, __shfl_xor_sync(0xffffffffu, s, 16));
    for (int q = 0; q < smax; q++) {
        float nv[16];
        #pragma unroll
        for (int i = 0; i < 16; i++) nv[i] = 0.f;
        #pragma unroll
        for (int k = 0; k < 16; k++) {
            float w = v[k];
            #pragma unroll
            for (int i = 0; i < 16; i++)
                nv[i] += __shfl_sync(0xffffffffu, v[i], k, 16) * w;
        }
        if (q < s) {
            #pragma unroll
            for (int i = 0; i < 16; i++) v[i] = nv[i];
        }
    }
    // store E^T: AexpT[row][m][n] = E[n][m]; lane holds E[i][j]=v[i] -> offset j*16+i (contiguous)
    float4* o = (float4*)(g_AexpT + (size_t)(r0 + r) * 256 + j * 16);
    o[0] = make_float4(v[0], v[1], v[2], v[3]);
    o[1] = make_float4(v[4], v[5], v[6], v[7]);
    o[2] = make_float4(v[8], v[9], v[10], v[11]);
    o[3] = make_float4(v[12], v[13], v[14], v[15]);
}

// ---------------- kernel 3a: per-chunk cumulative matrix P and local end-state e ----------------
__global__ __launch_bounds__(256) void k_chunk() {
    __shared__ float Ps[NS*17];
    __shared__ float Es[NS*17];
    __shared__ float es[NS];
    int gc = blockIdx.x;
    int tid = threadIdx.x;
    int i = tid >> 4, j = tid & 15;
    int r0 = gc * LCH;
    Ps[i*17 + j] = (i == j) ? 1.f : 0.f;
    if (tid < NS) es[tid] = 0.f;
    float cur    = g_AexpT[(size_t)r0 * 256 + tid];
    float bu_cur = (i == 0) ? g_Bu[(size_t)r0 * NS + j] : 0.f;
    __syncthreads();
    for (int t = 0; t < LCH; t++) {
        Es[i*17 + j] = cur;                       // Es[m][n] = E^T[m][n]
        __syncthreads();
        if (t + 1 < LCH) cur = g_AexpT[(size_t)(r0 + t + 1) * 256 + tid];
        float bu_next = (i == 0 && t + 1 < LCH) ? g_Bu[(size_t)(r0 + t + 1) * NS + j] : 0.f;
        float val = 0.f;
        #pragma unroll
        for (int k = 0; k < NS; k++) val += Ps[i*17 + k] * Es[j*17 + k];
        float ev = 0.f;
        if (i == 0) {
            ev = bu_cur;
            #pragma unroll
            for (int k = 0; k < NS; k++) ev += es[k] * Es[j*17 + k];
        }
        __syncthreads();
        Ps[i*17 + j] = val;
        if (i == 0) es[j] = ev;
        bu_cur = bu_next;
        __syncthreads();
    }
    g_PT[gc * 256 + tid] = Ps[(tid & 15)*17 + (tid >> 4)];   // PT[m][n] = P[n][m]
    if (tid < NS) g_e[gc * NS + tid] = es[tid];
}

// ---------------- kernel 3b: sequential chunk combine, warp per batch ----------------
__global__ __launch_bounds__(256) void k_combine() {
    int tid  = threadIdx.x;
    int b    = tid >> 5;
    int lane = tid & 31;
    int m    = lane & 15;
    float h = 0.f;
    for (int c = 0; c < CPB; c++) {
        int gc = b * CPB + c;
        if (lane < NS) g_hstart[gc * NS + lane] = h;
        const float4* p4 = (const float4*)(g_PT + gc * 256 + m * NS);
        float4 p0 = p4[0], p1 = p4[1], p2 = p4[2], p3 = p4[3];
        float acc = g_e[gc * NS + m];
        float hv[NS];
        #pragma unroll
        for (int n = 0; n < NS; n++) hv[n] = __shfl_sync(0xffffffffu, h, n, 32);
        acc += hv[0]*p0.x + hv[1]*p0.y + hv[2]*p0.z + hv[3]*p0.w
             + hv[4]*p1.x + hv[5]*p1.y + hv[6]*p1.z + hv[7]*p1.w
             + hv[8]*p2.x + hv[9]*p2.y + hv[10]*p2.z + hv[11]*p2.w
             + hv[12]*p3.x + hv[13]*p3.y + hv[14]*p3.z + hv[15]*p3.w;
        h = acc;
    }
}

// ---------------- kernel 3c: per-chunk matvec scan with known start state ----------------
__global__ __launch_bounds__(32) void k_scan() {
    int gc   = blockIdx.x;
    int lane = threadIdx.x & 31;
    int m    = lane & 15;
    int r0   = gc * LCH;
    float h = g_hstart[gc * NS + m];
    const float4* e4 = (const float4*)(g_AexpT + (size_t)r0 * 256 + m * NS);
    float4 a0 = e4[0], a1 = e4[1], a2 = e4[2], a3 = e4[3];
    float bu = g_Bu[(size_t)r0 * NS + m];
    for (int t = 0; t < LCH; t++) {
        float4 b0, b1, b2, b3; float bun = 0.f;
        if (t + 1 < LCH) {
            const float4* n4 = e4 + (size_t)(t + 1) * 64;
            b0 = n4[0]; b1 = n4[1]; b2 = n4[2]; b3 = n4[3];
            bun = g_Bu[(size_t)(r0 + t + 1) * NS + m];
        }
        float hv[NS];
        #pragma unroll
        for (int n = 0; n < NS; n++) hv[n] = __shfl_sync(0xffffffffu, h, n, 32);
        float acc = bu
            + hv[0]*a0.x + hv[1]*a0.y + hv[2]*a0.z + hv[3]*a0.w
            + hv[4]*a1.x + hv[5]*a1.y + hv[6]*a1.z + hv[7]*a1.w
            + hv[8]*a2.x + hv[9]*a2.y + hv[10]*a2.z + hv[11]*a2.w
            + hv[12]*a3.x + hv[13]*a3.y + hv[14]*a3.z + hv[15]*a3.w;
        h = acc;
        if (lane < NS) g_hs[(size_t)(r0 + t) * NS + m] = h;
        a0 = b0; a1 = b1; a2 = b2; a3 = b3; bu = bun;
    }
}

// ---------------- kernel 4: y = hs @ C^T + D*u ----------------
__global__ __launch_bounds__(256) void k_out(const float* __restrict__ u,
                                             const float* __restrict__ C,
                                             const float* __restrict__ D,
                                             float* __restrict__ y) {
    __shared__ float hs_s[16][NS];
    int tid = threadIdx.x;
    int d   = blockIdx.x * 256 + tid;
    int r0  = blockIdx.y * 16;
    hs_s[tid >> 4][tid & 15] = g_hs[(size_t)r0 * NS + tid];
    const float4* c4 = (const float4*)(C + (size_t)d * NS);
    float4 c0 = c4[0], c1 = c4[1], c2 = c4[2], c3 = c4[3];
    float Dd = D[d];
    __syncthreads();
    #pragma unroll 4
    for (int sl = 0; sl < 16; sl++) {
        size_t off = (size_t)(r0 + sl) * DIM + d;
        float yv = Dd * u[off];
        yv += hs_s[sl][0]*c0.x + hs_s[sl][1]*c0.y + hs_s[sl][2]*c0.z + hs_s[sl][3]*c0.w
            + hs_s[sl][4]*c1.x + hs_s[sl][5]*c1.y + hs_s[sl][6]*c1.z + hs_s[sl][7]*c1.w
            + hs_s[sl][8]*c2.x + hs_s[sl][9]*c2.y + hs_s[sl][10]*c2.z + hs_s[sl][11]*c2.w
            + hs_s[sl][12]*c3.x + hs_s[sl][13]*c3.y + hs_s[sl][14]*c3.z + hs_s[sl][15]*c3.w;
        y[off] = yv;
    }
}

// ---------------- launch ----------------
extern "C" void kernel_launch(void* const* d_in, const int* in_sizes, int n_in,
                              void* d_out, int out_size) {
    const float* u     = (const float*)d_in[0];
    const float* gate  = (const float*)d_in[1];
    const float* A_log = (const float*)d_in[2];
    const float* B_mat = (const float*)d_in[3];
    const float* C_mat = (const float*)d_in[4];
    const float* D     = (const float*)d_in[5];
    const float* dt_w  = (const float*)d_in[6];
    const float* dt_b  = (const float*)d_in[7];
    float* y = (float*)d_out;

    k_prepA<<<1, 256>>>(A_log);
    k_delta<<<ROWS/8, 256>>>(gate, dt_w, dt_b);
    k_bu<<<ROWS/16, 256>>>(u, B_mat);
    k_expm<<<ROWS/16, 256>>>();
    k_chunk<<<NCHUNK, 256>>>();
    k_combine<<<1, 256>>>();
    k_scan<<<NCHUNK, 32>>>();
    k_out<<<dim3(DIM/256, ROWS/16), 256>>>(u, C_mat, D, y);
}

// round 5
// speedup vs baseline: 2.1198x; 1.2344x over previous
#include <cuda_runtime.h>

#define BATCHN 8
#define SEQ    2048
#define DIM    1024
#define NS     16
#define ROWS   (BATCHN*SEQ)     // 16384
#define LCH    32               // chunk length
#define CPB    (SEQ/LCH)        // 64 chunks per batch
#define NCHUNK (BATCHN*CPB)     // 512 chunks
#define NTERMS 21               // Taylor degree 20
#define THETA  5.2f

// ---------------- scratch (static device globals; no runtime alloc) ----------------
__device__ float g_Anorm;
__device__ __align__(128) float g_Pd[NTERMS*256];              // A^k / k!
__device__ __align__(128) float g_delta[ROWS];
__device__ __align__(128) float g_Bu[ROWS*NS];
__device__ __align__(128) float g_AexpT[(size_t)ROWS*NS*NS];   // 16 MB, E^T per row: [r][m][n] = E[n][m]
__device__ __align__(128) float g_PT[NCHUNK*NS*NS];            // chunk product transposed
__device__ __align__(128) float g_e[NCHUNK*NS];                // chunk local end-state
__device__ __align__(128) float g_hstart[NCHUNK*NS];           // state at chunk start
__device__ __align__(128) float g_hs[(size_t)ROWS*NS];

// ---------------- f32x2 helpers ----------------
__device__ __forceinline__ unsigned long long pk2(float lo, float hi) {
    unsigned long long r;
    asm("mov.b64 %0, {%1, %2};" : "=l"(r) : "f"(lo), "f"(hi));
    return r;
}
__device__ __forceinline__ float2 upk2(unsigned long long v) {
    float2 r;
    asm("mov.b64 {%0, %1}, %2;" : "=f"(r.x), "=f"(r.y) : "l"(v));
    return r;
}
__device__ __forceinline__ void fma2(unsigned long long& d, unsigned long long a, unsigned long long b) {
    asm("fma.rn.f32x2 %0, %1, %2, %0;" : "+l"(d) : "l"(a), "l"(b));
}

// ---------------- kernel 0: A = -exp(A_log), inf-norm, P_k = A^k/k! ----------------
__global__ __launch_bounds__(256) void k_prepA(const float* __restrict__ A_log) {
    __shared__ float As[256];
    __shared__ float cur[256];
    __shared__ float rowsum[NS];
    int tid = threadIdx.x;
    int i = tid >> 4, j = tid & 15;
    float a = -expf(A_log[tid]);
    As[tid] = a;
    __syncthreads();
    if (tid < NS) {
        float s = 0.f;
        #pragma unroll
        for (int c = 0; c < NS; c++) s += fabsf(As[tid*NS + c]);
        rowsum[tid] = s;
    }
    __syncthreads();
    if (tid == 0) {
        float m = 0.f;
        #pragma unroll
        for (int r = 0; r < NS; r++) m = fmaxf(m, rowsum[r]);
        g_Anorm = m;
    }
    float id = (i == j) ? 1.f : 0.f;
    cur[tid] = id;
    g_Pd[tid] = id;
    __syncthreads();
    for (int k = 1; k < NTERMS; k++) {
        float acc = 0.f;
        #pragma unroll
        for (int kk = 0; kk < NS; kk++) acc += cur[i*NS + kk] * As[kk*NS + j];
        acc *= (1.f / (float)k);
        __syncthreads();
        cur[tid] = acc;
        g_Pd[k*256 + tid] = acc;
        __syncthreads();
    }
}

// ---------------- kernel 1a: delta = sigmoid(gate . dt_w + dt_b), warp per row ----------------
__global__ __launch_bounds__(256) void k_delta(const float* __restrict__ gate,
                                               const float* __restrict__ dt_w,
                                               const float* __restrict__ dt_b) {
    int warp = (blockIdx.x * blockDim.x + threadIdx.x) >> 5;
    int lane = threadIdx.x & 31;
    if (warp >= ROWS) return;
    const float4* g4 = (const float4*)(gate + (size_t)warp * DIM);
    const float4* w4 = (const float4*)dt_w;
    float acc = 0.f;
    #pragma unroll
    for (int i = 0; i < 8; i++) {
        float4 g = g4[lane + 32*i];
        float4 w = w4[lane + 32*i];
        acc += g.x*w.x + g.y*w.y + g.z*w.z + g.w*w.w;
    }
    #pragma unroll
    for (int o = 16; o; o >>= 1) acc += __shfl_xor_sync(0xffffffffu, acc, o);
    if (lane == 0) g_delta[warp] = 1.f / (1.f + expf(-(acc + dt_b[0])));
}

// ---------------- kernel 1b: Bu = u @ B_mat, register-tiled + f32x2 ----------------
// Block: 128 rows x 16 n, K split in halves across tid>>7. Thread: 2 rows x 8 n,
// k processed in pairs packed into f32x2 FFMA.
__global__ __launch_bounds__(256) void k_bu(const float* __restrict__ u,
                                            const float* __restrict__ B) {
    __shared__ __align__(16) float usb[128*33];     // [row][k] pad 33
    __shared__ __align__(16) float Bst[16*34];      // [n][k]  pad 34
    int tid  = threadIdx.x;
    int ks   = tid >> 7;              // k-split half
    int ngrp = (tid >> 6) & 1;        // n group (8 each)
    int rowp = tid & 63;              // row pair
    int r0   = blockIdx.x * 128;

    unsigned long long a0[8], a1[8];
    #pragma unroll
    for (int nn = 0; nn < 8; nn++) { a0[nn] = 0ull; a1[nn] = 0ull; }

    int lrow = tid >> 3, lq = tid & 7;            // u loader mapping
    int bkk  = tid >> 3, bnp = tid & 7;           // B loader mapping
    float4 pu[4]; float2 pb;
    // prefetch tile 0
    #pragma unroll
    for (int it = 0; it < 4; it++)
        pu[it] = *(const float4*)&u[(size_t)(r0 + lrow + it*32) * DIM + lq*4];
    pb = *(const float2*)&B[(size_t)bkk * NS + bnp*2];

    for (int t = 0; t < 32; t++) {
        // store prefetched tile
        #pragma unroll
        for (int it = 0; it < 4; it++) {
            int row = lrow + it*32;
            usb[row*33 + lq*4 + 0] = pu[it].x;
            usb[row*33 + lq*4 + 1] = pu[it].y;
            usb[row*33 + lq*4 + 2] = pu[it].z;
            usb[row*33 + lq*4 + 3] = pu[it].w;
        }
        Bst[(2*bnp + 0)*34 + bkk] = pb.x;
        Bst[(2*bnp + 1)*34 + bkk] = pb.y;
        __syncthreads();
        if (t + 1 < 32) {
            int kt = (t + 1) * 32;
            #pragma unroll
            for (int it = 0; it < 4; it++)
                pu[it] = *(const float4*)&u[(size_t)(r0 + lrow + it*32) * DIM + kt + lq*4];
            pb = *(const float2*)&B[(size_t)(kt + bkk) * NS + bnp*2];
        }
        int kb = ks * 16;
        #pragma unroll
        for (int kk = 0; kk < 8; kk++) {
            int k = kb + 2*kk;
            unsigned long long ua = *(const unsigned long long*)&usb[(2*rowp)*33 + k];
            const float* ur1 = &usb[(2*rowp + 1)*33 + k];
            unsigned long long ub = pk2(ur1[0], ur1[1]);
            #pragma unroll
            for (int nn = 0; nn < 8; nn++) {
                unsigned long long bb = *(const unsigned long long*)&Bst[(8*ngrp + nn)*34 + k];
                fma2(a0[nn], ua, bb);
                fma2(a1[nn], ub, bb);
            }
        }
        __syncthreads();
    }
    // reduce across k-split halves
    float* red = usb;     // reuse: need 128*16 floats
    if (ks == 1) {
        int p = tid - 128;
        #pragma unroll
        for (int nn = 0; nn < 8; nn++) {
            float2 x0 = upk2(a0[nn]); float2 x1 = upk2(a1[nn]);
            red[p*16 + nn]     = x0.x + x0.y;
            red[p*16 + 8 + nn] = x1.x + x1.y;
        }
    }
    __syncthreads();
    if (ks == 0) {
        #pragma unroll
        for (int nn = 0; nn < 8; nn++) {
            float2 x0 = upk2(a0[nn]); float2 x1 = upk2(a1[nn]);
            float v0 = x0.x + x0.y + red[tid*16 + nn];
            float v1 = x1.x + x1.y + red[tid*16 + 8 + nn];
            g_Bu[(size_t)(r0 + 2*rowp)     * NS + 8*ngrp + nn] = v0;
            g_Bu[(size_t)(r0 + 2*rowp + 1) * NS + 8*ngrp + nn] = v1;
        }
    }
}

// ---------------- kernel 2: E = expm(delta*A); Taylor-20 + <=2 squarings ----------------
__global__ __launch_bounds__(256) void k_expm() {
    __shared__ float Ts[16*257];
    __shared__ float ys[16];
    __shared__ int   ss[16];
    int tid = threadIdx.x;
    int r0 = blockIdx.x * 16;
    if (tid < 16) {
        float d = g_delta[r0 + tid];
        float nn = d * g_Anorm;
        int s = 0;
        while (nn > THETA) { nn *= 0.5f; s++; }
        ss[tid] = s;
        ys[tid] = ldexpf(d, -s);
    }
    float p[NTERMS];
    #pragma unroll
    for (int k = 0; k < NTERMS; k++) p[k] = g_Pd[k*256 + tid];
    __syncthreads();
    #pragma unroll
    for (int r = 0; r < 16; r++) {
        float y = ys[r];
        float acc = p[NTERMS-1];
        #pragma unroll
        for (int k = NTERMS-2; k >= 0; k--) acc = acc*y + p[k];
        Ts[r*257 + tid] = acc;
    }
    __syncthreads();
    int r = tid >> 4, j = tid & 15;
    float v[16];
    #pragma unroll
    for (int i = 0; i < 16; i++) v[i] = Ts[r*257 + i*16 + j];   // v = T[:,j] of row r
    int s = ss[r];
    int smax = max(s, __shfl_xor_sync(0xffffffffu, s, 16));
    for (int q = 0; q < smax; q++) {
        float nv[16];
        #pragma unroll
        for (int i = 0; i < 16; i++) nv[i] = 0.f;
        #pragma unroll
        for (int k = 0; k < 16; k++) {
            float w = v[k];
            #pragma unroll
            for (int i = 0; i < 16; i++)
                nv[i] += __shfl_sync(0xffffffffu, v[i], k, 16) * w;
        }
        if (q < s) {
            #pragma unroll
            for (int i = 0; i < 16; i++) v[i] = nv[i];
        }
    }
    // store E^T: AexpT[row][m][n] = E[n][m]; lane holds E[i][j]=v[i] -> offset j*16+i (contiguous)
    float4* o = (float4*)(g_AexpT + (size_t)(r0 + r) * 256 + j * 16);
    o[0] = make_float4(v[0], v[1], v[2], v[3]);
    o[1] = make_float4(v[4], v[5], v[6], v[7]);
    o[2] = make_float4(v[8], v[9], v[10], v[11]);
    o[3] = make_float4(v[12], v[13], v[14], v[15]);
}

// ---------------- kernel 3a: per-chunk cumulative matrix P and local end-state e ----------------
// Ping-pong P and E buffers: 1 barrier per step, LDG-prefetched E.
__global__ __launch_bounds__(256) void k_chunk() {
    __shared__ __align__(16) float Ps[2][16*20];
    __shared__ __align__(16) float Es[2][16*20];
    __shared__ float esm[2][16];
    int gc = blockIdx.x;
    int tid = threadIdx.x;
    int i = tid >> 4, j = tid & 15;
    int r0 = gc * LCH;
    Ps[0][i*20 + j] = (i == j) ? 1.f : 0.f;
    if (tid < 16) esm[0][tid] = 0.f;
    Es[0][i*20 + j] = g_AexpT[(size_t)r0 * 256 + tid];
    float bu_cur = (i == 0) ? g_Bu[(size_t)r0 * NS + j] : 0.f;
    __syncthreads();
    int cur = 0;
    for (int t = 0; t < LCH; t++) {
        int eb = t & 1;
        float enext = 0.f, bunext = 0.f;
        if (t + 1 < LCH) {
            enext = g_AexpT[(size_t)(r0 + t + 1) * 256 + tid];
            if (i == 0) bunext = g_Bu[(size_t)(r0 + t + 1) * NS + j];
        }
        const float* Pr = &Ps[cur][i*20];
        const float* Ec = &Es[eb][j*20];       // Ec[k] = E[k][j]
        float val = 0.f;
        #pragma unroll
        for (int k = 0; k < 16; k++) val += Pr[k] * Ec[k];
        float ev = 0.f;
        if (i == 0) {
            ev = bu_cur;
            #pragma unroll
            for (int k = 0; k < 16; k++) ev += esm[cur][k] * Ec[k];
        }
        if (t + 1 < LCH) Es[eb ^ 1][i*20 + j] = enext;
        Ps[cur ^ 1][i*20 + j] = val;
        if (i == 0) esm[cur ^ 1][j] = ev;
        bu_cur = bunext;
        cur ^= 1;
        __syncthreads();
    }
    g_PT[gc * 256 + tid] = Ps[cur][j*20 + i];   // PT[m][n] = P[n][m]
    if (tid < 16) g_e[gc * NS + tid] = esm[cur][tid];
}

// ---------------- kernel 3b: sequential chunk combine, warp per batch, prefetched ----------------
__global__ __launch_bounds__(256) void k_combine() {
    int tid  = threadIdx.x;
    int b    = tid >> 5;
    int lane = tid & 31;
    int m    = lane & 15;
    float h = 0.f;
    int gc0 = b * CPB;
    const float4* p4 = (const float4*)(g_PT + gc0 * 256 + m * NS);
    float4 p0 = p4[0], p1 = p4[1], p2 = p4[2], p3 = p4[3];
    float e = g_e[gc0 * NS + m];
    for (int c = 0; c < CPB; c++) {
        int gc = gc0 + c;
        if (lane < NS) g_hstart[gc * NS + lane] = h;
        float4 q0, q1, q2, q3; float en = 0.f;
        if (c + 1 < CPB) {
            const float4* n4 = (const float4*)(g_PT + (gc + 1) * 256 + m * NS);
            q0 = n4[0]; q1 = n4[1]; q2 = n4[2]; q3 = n4[3];
            en = g_e[(gc + 1) * NS + m];
        }
        float hv[NS];
        #pragma unroll
        for (int n = 0; n < NS; n++) hv[n] = __shfl_sync(0xffffffffu, h, n, 32);
        float acc = e
             + hv[0]*p0.x + hv[1]*p0.y + hv[2]*p0.z + hv[3]*p0.w
             + hv[4]*p1.x + hv[5]*p1.y + hv[6]*p1.z + hv[7]*p1.w
             + hv[8]*p2.x + hv[9]*p2.y + hv[10]*p2.z + hv[11]*p2.w
             + hv[12]*p3.x + hv[13]*p3.y + hv[14]*p3.z + hv[15]*p3.w;
        h = acc;
        p0 = q0; p1 = q1; p2 = q2; p3 = q3; e = en;
    }
}

// ---------------- kernel 3c: per-chunk matvec scan with known start state ----------------
__global__ __launch_bounds__(32) void k_scan() {
    int gc   = blockIdx.x;
    int lane = threadIdx.x & 31;
    int m    = lane & 15;
    int r0   = gc * LCH;
    float h = g_hstart[gc * NS + m];
    const float4* e4 = (const float4*)(g_AexpT + (size_t)r0 * 256 + m * NS);
    float4 a0 = e4[0], a1 = e4[1], a2 = e4[2], a3 = e4[3];
    float bu = g_Bu[(size_t)r0 * NS + m];
    for (int t = 0; t < LCH; t++) {
        float4 b0, b1, b2, b3; float bun = 0.f;
        if (t + 1 < LCH) {
            const float4* n4 = e4 + (size_t)(t + 1) * 64;
            b0 = n4[0]; b1 = n4[1]; b2 = n4[2]; b3 = n4[3];
            bun = g_Bu[(size_t)(r0 + t + 1) * NS + m];
        }
        float hv[NS];
        #pragma unroll
        for (int n = 0; n < NS; n++) hv[n] = __shfl_sync(0xffffffffu, h, n, 32);
        float acc = bu
            + hv[0]*a0.x + hv[1]*a0.y + hv[2]*a0.z + hv[3]*a0.w
            + hv[4]*a1.x + hv[5]*a1.y + hv[6]*a1.z + hv[7]*a1.w
            + hv[8]*a2.x + hv[9]*a2.y + hv[10]*a2.z + hv[11]*a2.w
            + hv[12]*a3.x + hv[13]*a3.y + hv[14]*a3.z + hv[15]*a3.w;
        h = acc;
        if (lane < NS) g_hs[(size_t)(r0 + t) * NS + m] = h;
        a0 = b0; a1 = b1; a2 = b2; a3 = b3; bu = bun;
    }
}

// ---------------- kernel 4: y = hs @ C^T + D*u ----------------
__global__ __launch_bounds__(256) void k_out(const float* __restrict__ u,
                                             const float* __restrict__ C,
                                             const float* __restrict__ D,
                                             float* __restrict__ y) {
    __shared__ float hs_s[16][NS];
    int tid = threadIdx.x;
    int d   = blockIdx.x * 256 + tid;
    int r0  = blockIdx.y * 16;
    hs_s[tid >> 4][tid & 15] = g_hs[(size_t)r0 * NS + tid];
    const float4* c4 = (const float4*)(C + (size_t)d * NS);
    float4 c0 = c4[0], c1 = c4[1], c2 = c4[2], c3 = c4[3];
    float Dd = D[d];
    __syncthreads();
    #pragma unroll 4
    for (int sl = 0; sl < 16; sl++) {
        size_t off = (size_t)(r0 + sl) * DIM + d;
        float yv = Dd * u[off];
        yv += hs_s[sl][0]*c0.x + hs_s[sl][1]*c0.y + hs_s[sl][2]*c0.z + hs_s[sl][3]*c0.w
            + hs_s[sl][4]*c1.x + hs_s[sl][5]*c1.y + hs_s[sl][6]*c1.z + hs_s[sl][7]*c1.w
            + hs_s[sl][8]*c2.x + hs_s[sl][9]*c2.y + hs_s[sl][10]*c2.z + hs_s[sl][11]*c2.w
            + hs_s[sl][12]*c3.x + hs_s[sl][13]*c3.y + hs_s[sl][14]*c3.z + hs_s[sl][15]*c3.w;
        y[off] = yv;
    }
}

// ---------------- launch ----------------
extern "C" void kernel_launch(void* const* d_in, const int* in_sizes, int n_in,
                              void* d_out, int out_size) {
    const float* u     = (const float*)d_in[0];
    const float* gate  = (const float*)d_in[1];
    const float* A_log = (const float*)d_in[2];
    const float* B_mat = (const float*)d_in[3];
    const float* C_mat = (const float*)d_in[4];
    const float* D     = (const float*)d_in[5];
    const float* dt_w  = (const float*)d_in[6];
    const float* dt_b  = (const float*)d_in[7];
    float* y = (float*)d_out;

    k_prepA<<<1, 256>>>(A_log);
    k_delta<<<ROWS/8, 256>>>(gate, dt_w, dt_b);
    k_bu<<<ROWS/128, 256>>>(u, B_mat);
    k_expm<<<ROWS/16, 256>>>();
    k_chunk<<<NCHUNK, 256>>>();
    k_combine<<<1, 256>>>();
    k_scan<<<NCHUNK, 32>>>();
    k_out<<<dim3(DIM/256, ROWS/16), 256>>>(u, C_mat, D, y);
}

// round 6
// speedup vs baseline: 2.4993x; 1.1790x over previous
#include <cuda_runtime.h>

#define BATCHN 8
#define SEQ    2048
#define DIM    1024
#define NS     16
#define ROWS   (BATCHN*SEQ)     // 16384
#define LCH    32               // chunk length
#define CPB    (SEQ/LCH)        // 64 chunks per batch
#define NCHUNK (BATCHN*CPB)     // 512 chunks
#define NTERMS 21               // Taylor degree 20
#define THETA  5.2f

// ---------------- scratch (static device globals; no runtime alloc) ----------------
__device__ float g_Anorm;
__device__ __align__(128) float g_Pd[NTERMS*256];              // A^k / k!
__device__ __align__(128) float g_delta[ROWS];
__device__ __align__(128) float g_Bu[ROWS*NS];
__device__ __align__(128) float g_AexpT[(size_t)ROWS*NS*NS];   // 16 MB, E^T per row: [r][m][n] = E[n][m]
__device__ __align__(128) float g_PT[NCHUNK*NS*NS];            // chunk product transposed
__device__ __align__(128) float g_e[NCHUNK*NS];                // chunk local end-state
__device__ __align__(128) float g_hstart[NCHUNK*NS];           // state at chunk start
__device__ __align__(128) float g_hs[(size_t)ROWS*NS];

// ---------------- f32x2 helpers ----------------
__device__ __forceinline__ unsigned long long pk2(float lo, float hi) {
    unsigned long long r;
    asm("mov.b64 %0, {%1, %2};" : "=l"(r) : "f"(lo), "f"(hi));
    return r;
}
__device__ __forceinline__ float2 upk2(unsigned long long v) {
    float2 r;
    asm("mov.b64 {%0, %1}, %2;" : "=f"(r.x), "=f"(r.y) : "l"(v));
    return r;
}
__device__ __forceinline__ void fma2(unsigned long long& d, unsigned long long a, unsigned long long b) {
    asm("fma.rn.f32x2 %0, %1, %2, %0;" : "+l"(d) : "l"(a), "l"(b));
}

// ---------------- kernel 0: A = -exp(A_log), inf-norm, P_k = A^k/k! ----------------
__global__ __launch_bounds__(256) void k_prepA(const float* __restrict__ A_log) {
    __shared__ float As[256];
    __shared__ float cur[256];
    __shared__ float rowsum[NS];
    int tid = threadIdx.x;
    int i = tid >> 4, j = tid & 15;
    float a = -expf(A_log[tid]);
    As[tid] = a;
    __syncthreads();
    if (tid < NS) {
        float s = 0.f;
        #pragma unroll
        for (int c = 0; c < NS; c++) s += fabsf(As[tid*NS + c]);
        rowsum[tid] = s;
    }
    __syncthreads();
    if (tid == 0) {
        float m = 0.f;
        #pragma unroll
        for (int r = 0; r < NS; r++) m = fmaxf(m, rowsum[r]);
        g_Anorm = m;
    }
    float id = (i == j) ? 1.f : 0.f;
    cur[tid] = id;
    g_Pd[tid] = id;
    __syncthreads();
    for (int k = 1; k < NTERMS; k++) {
        float acc = 0.f;
        #pragma unroll
        for (int kk = 0; kk < NS; kk++) acc += cur[i*NS + kk] * As[kk*NS + j];
        acc *= (1.f / (float)k);
        __syncthreads();
        cur[tid] = acc;
        g_Pd[k*256 + tid] = acc;
        __syncthreads();
    }
}

// ---------------- kernel 1a: delta = sigmoid(gate . dt_w + dt_b), warp per row ----------------
__global__ __launch_bounds__(256) void k_delta(const float* __restrict__ gate,
                                               const float* __restrict__ dt_w,
                                               const float* __restrict__ dt_b) {
    int warp = (blockIdx.x * blockDim.x + threadIdx.x) >> 5;
    int lane = threadIdx.x & 31;
    if (warp >= ROWS) return;
    const float4* g4 = (const float4*)(gate + (size_t)warp * DIM);
    const float4* w4 = (const float4*)dt_w;
    float acc = 0.f;
    #pragma unroll
    for (int i = 0; i < 8; i++) {
        float4 g = g4[lane + 32*i];
        float4 w = w4[lane + 32*i];
        acc += g.x*w.x + g.y*w.y + g.z*w.z + g.w*w.w;
    }
    #pragma unroll
    for (int o = 16; o; o >>= 1) acc += __shfl_xor_sync(0xffffffffu, acc, o);
    if (lane == 0) g_delta[warp] = 1.f / (1.f + expf(-(acc + dt_b[0])));
}

// ---------------- kernel 1b: Bu = u @ B_mat, register-tiled + f32x2 ----------------
__global__ __launch_bounds__(256, 1) void k_bu(const float* __restrict__ u,
                                               const float* __restrict__ B) {
    __shared__ __align__(16) float usb[128*33];     // [row][k] pad 33
    __shared__ __align__(16) float Bst[16*34];      // [n][k]  pad 34
    int tid  = threadIdx.x;
    int ks   = tid >> 7;              // k-split half
    int ngrp = (tid >> 6) & 1;        // n group (8 each)
    int rowp = tid & 63;              // row pair
    int r0   = blockIdx.x * 128;

    unsigned long long a0[8], a1[8];
    #pragma unroll
    for (int nn = 0; nn < 8; nn++) { a0[nn] = 0ull; a1[nn] = 0ull; }

    int lrow = tid >> 3, lq = tid & 7;            // u loader mapping
    int bkk  = tid >> 3, bnp = tid & 7;           // B loader mapping
    float4 pu[4]; float2 pb;
    #pragma unroll
    for (int it = 0; it < 4; it++)
        pu[it] = *(const float4*)&u[(size_t)(r0 + lrow + it*32) * DIM + lq*4];
    pb = *(const float2*)&B[(size_t)bkk * NS + bnp*2];

    for (int t = 0; t < 32; t++) {
        #pragma unroll
        for (int it = 0; it < 4; it++) {
            int row = lrow + it*32;
            usb[row*33 + lq*4 + 0] = pu[it].x;
            usb[row*33 + lq*4 + 1] = pu[it].y;
            usb[row*33 + lq*4 + 2] = pu[it].z;
            usb[row*33 + lq*4 + 3] = pu[it].w;
        }
        Bst[(2*bnp + 0)*34 + bkk] = pb.x;
        Bst[(2*bnp + 1)*34 + bkk] = pb.y;
        __syncthreads();
        if (t + 1 < 32) {
            int kt = (t + 1) * 32;
            #pragma unroll
            for (int it = 0; it < 4; it++)
                pu[it] = *(const float4*)&u[(size_t)(r0 + lrow + it*32) * DIM + kt + lq*4];
            pb = *(const float2*)&B[(size_t)(kt + bkk) * NS + bnp*2];
        }
        int kb = ks * 16;
        #pragma unroll
        for (int kk = 0; kk < 8; kk++) {
            int k = kb + 2*kk;
            unsigned long long ua = *(const unsigned long long*)&usb[(2*rowp)*33 + k];
            const float* ur1 = &usb[(2*rowp + 1)*33 + k];
            unsigned long long ub = pk2(ur1[0], ur1[1]);
            #pragma unroll
            for (int nn = 0; nn < 8; nn++) {
                unsigned long long bb = *(const unsigned long long*)&Bst[(8*ngrp + nn)*34 + k];
                fma2(a0[nn], ua, bb);
                fma2(a1[nn], ub, bb);
            }
        }
        __syncthreads();
    }
    float* red = usb;
    if (ks == 1) {
        int p = tid - 128;
        #pragma unroll
        for (int nn = 0; nn < 8; nn++) {
            float2 x0 = upk2(a0[nn]); float2 x1 = upk2(a1[nn]);
            red[p*16 + nn]     = x0.x + x0.y;
            red[p*16 + 8 + nn] = x1.x + x1.y;
        }
    }
    __syncthreads();
    if (ks == 0) {
        #pragma unroll
        for (int nn = 0; nn < 8; nn++) {
            float2 x0 = upk2(a0[nn]); float2 x1 = upk2(a1[nn]);
            float v0 = x0.x + x0.y + red[tid*16 + nn];
            float v1 = x1.x + x1.y + red[tid*16 + 8 + nn];
            g_Bu[(size_t)(r0 + 2*rowp)     * NS + 8*ngrp + nn] = v0;
            g_Bu[(size_t)(r0 + 2*rowp + 1) * NS + 8*ngrp + nn] = v1;
        }
    }
}

// ---------------- kernel 2: E = expm(delta*A); Taylor-20 + <=2 squarings ----------------
__global__ __launch_bounds__(256, 1) void k_expm() {
    __shared__ float Ts[16*257];
    __shared__ float ys[16];
    __shared__ int   ss[16];
    int tid = threadIdx.x;
    int r0 = blockIdx.x * 16;
    if (tid < 16) {
        float d = g_delta[r0 + tid];
        float nn = d * g_Anorm;
        int s = 0;
        while (nn > THETA) { nn *= 0.5f; s++; }
        ss[tid] = s;
        ys[tid] = ldexpf(d, -s);
    }
    float p[NTERMS];
    #pragma unroll
    for (int k = 0; k < NTERMS; k++) p[k] = g_Pd[k*256 + tid];
    __syncthreads();
    #pragma unroll
    for (int r = 0; r < 16; r++) {
        float y = ys[r];
        float acc = p[NTERMS-1];
        #pragma unroll
        for (int k = NTERMS-2; k >= 0; k--) acc = acc*y + p[k];
        Ts[r*257 + tid] = acc;
    }
    __syncthreads();
    int r = tid >> 4, j = tid & 15;
    float v[16];
    #pragma unroll
    for (int i = 0; i < 16; i++) v[i] = Ts[r*257 + i*16 + j];   // v = T[:,j] of row r
    int s = ss[r];
    int smax = max(s, __shfl_xor_sync(0xffffffffu, s, 16));
    for (int q = 0; q < smax; q++) {
        float nv[16];
        #pragma unroll
        for (int i = 0; i < 16; i++) nv[i] = 0.f;
        #pragma unroll
        for (int k = 0; k < 16; k++) {
            float w = v[k];
            #pragma unroll
            for (int i = 0; i < 16; i++)
                nv[i] += __shfl_sync(0xffffffffu, v[i], k, 16) * w;
        }
        if (q < s) {
            #pragma unroll
            for (int i = 0; i < 16; i++) v[i] = nv[i];
        }
    }
    float4* o = (float4*)(g_AexpT + (size_t)(r0 + r) * 256 + j * 16);
    o[0] = make_float4(v[0], v[1], v[2], v[3]);
    o[1] = make_float4(v[4], v[5], v[6], v[7]);
    o[2] = make_float4(v[8], v[9], v[10], v[11]);
    o[3] = make_float4(v[12], v[13], v[14], v[15]);
}

// ---------------- kernel 3a: chunk products; ping-pong shared + 4-deep reg prefetch ----------------
__global__ __launch_bounds__(256) void k_chunk() {
    __shared__ __align__(16) float Ps[2][16*20];
    __shared__ __align__(16) float Es[2][16*20];
    __shared__ float esm[2][16];
    int gc = blockIdx.x;
    int tid = threadIdx.x;
    int i = tid >> 4, j = tid & 15;
    int r0 = gc * LCH;
    Ps[0][i*20 + j] = (i == j) ? 1.f : 0.f;
    if (tid < 16) esm[0][tid] = 0.f;
    float ep[4], bup[4];
    #pragma unroll
    for (int k = 0; k < 4; k++) {
        ep[k] = g_AexpT[(size_t)(r0 + k) * 256 + tid];
        bup[k] = (i == 0) ? g_Bu[(size_t)(r0 + k) * NS + j] : 0.f;
    }
    Es[0][i*20 + j] = ep[0];
    __syncthreads();
    int cur = 0;
    #pragma unroll 4
    for (int t = 0; t < LCH; t++) {
        const float* Pr = &Ps[cur][i*20];
        const float* Ec = &Es[t & 1][j*20];       // Ec[k] = E[k][j]
        float val = 0.f;
        #pragma unroll
        for (int k = 0; k < 16; k++) val += Pr[k] * Ec[k];
        float ev = 0.f;
        if (i == 0) {
            ev = bup[t & 3];
            #pragma unroll
            for (int k = 0; k < 16; k++) ev += esm[cur][k] * Ec[k];
        }
        if (t + 1 < LCH) Es[(t + 1) & 1][i*20 + j] = ep[(t + 1) & 3];
        if (t + 4 < LCH) {
            ep[t & 3] = g_AexpT[(size_t)(r0 + t + 4) * 256 + tid];
            if (i == 0) bup[t & 3] = g_Bu[(size_t)(r0 + t + 4) * NS + j];
        }
        Ps[cur ^ 1][i*20 + j] = val;
        if (i == 0) esm[cur ^ 1][j] = ev;
        cur ^= 1;
        __syncthreads();
    }
    g_PT[gc * 256 + tid] = Ps[cur][j*20 + i];   // PT[m][n] = P[n][m]
    if (tid < 16) g_e[gc * NS + tid] = esm[cur][tid];
}

// ---------------- kernel 3b: sequential chunk combine, warp per batch, 4-deep prefetch ----------------
__global__ __launch_bounds__(256, 1) void k_combine() {
    int tid  = threadIdx.x;
    int b    = tid >> 5;
    int lane = tid & 31;
    int m    = lane & 15;
    float h = 0.f;
    int gc0 = b * CPB;
    float4 P4[4][4]; float ee[4];
    #pragma unroll
    for (int k = 0; k < 4; k++) {
        const float4* p4 = (const float4*)(g_PT + (gc0 + k) * 256 + m * NS);
        P4[k][0] = p4[0]; P4[k][1] = p4[1]; P4[k][2] = p4[2]; P4[k][3] = p4[3];
        ee[k] = g_e[(gc0 + k) * NS + m];
    }
    #pragma unroll 4
    for (int c = 0; c < CPB; c++) {
        int sl = c & 3;
        int gc = gc0 + c;
        if (lane < NS) g_hstart[gc * NS + lane] = h;
        float4 p0 = P4[sl][0], p1 = P4[sl][1], p2 = P4[sl][2], p3 = P4[sl][3];
        float e = ee[sl];
        if (c + 4 < CPB) {
            const float4* n4 = (const float4*)(g_PT + (gc + 4) * 256 + m * NS);
            P4[sl][0] = n4[0]; P4[sl][1] = n4[1]; P4[sl][2] = n4[2]; P4[sl][3] = n4[3];
            ee[sl] = g_e[(gc + 4) * NS + m];
        }
        float hv[NS];
        #pragma unroll
        for (int n = 0; n < NS; n++) hv[n] = __shfl_sync(0xffffffffu, h, n, 32);
        float acc = e
             + hv[0]*p0.x + hv[1]*p0.y + hv[2]*p0.z + hv[3]*p0.w
             + hv[4]*p1.x + hv[5]*p1.y + hv[6]*p1.z + hv[7]*p1.w
             + hv[8]*p2.x + hv[9]*p2.y + hv[10]*p2.z + hv[11]*p2.w
             + hv[12]*p3.x + hv[13]*p3.y + hv[14]*p3.z + hv[15]*p3.w;
        h = acc;
    }
}

// ---------------- kernel 3c: per-chunk matvec scan, 4-deep prefetch ----------------
__global__ __launch_bounds__(32) void k_scan() {
    int gc   = blockIdx.x;
    int lane = threadIdx.x & 31;
    int m    = lane & 15;
    int r0   = gc * LCH;
    float h = g_hstart[gc * NS + m];
    const float4* base = (const float4*)(g_AexpT + (size_t)r0 * 256 + m * NS);
    float4 Ea[4][4]; float bub[4];
    #pragma unroll
    for (int k = 0; k < 4; k++) {
        const float4* p = base + (size_t)k * 64;
        Ea[k][0] = p[0]; Ea[k][1] = p[1]; Ea[k][2] = p[2]; Ea[k][3] = p[3];
        bub[k] = g_Bu[(size_t)(r0 + k) * NS + m];
    }
    #pragma unroll 4
    for (int t = 0; t < LCH; t++) {
        int sl = t & 3;
        float4 a0 = Ea[sl][0], a1 = Ea[sl][1], a2 = Ea[sl][2], a3 = Ea[sl][3];
        float bu = bub[sl];
        if (t + 4 < LCH) {
            const float4* p = base + (size_t)(t + 4) * 64;
            Ea[sl][0] = p[0]; Ea[sl][1] = p[1]; Ea[sl][2] = p[2]; Ea[sl][3] = p[3];
            bub[sl] = g_Bu[(size_t)(r0 + t + 4) * NS + m];
        }
        float hv[NS];
        #pragma unroll
        for (int n = 0; n < NS; n++) hv[n] = __shfl_sync(0xffffffffu, h, n, 32);
        float acc = bu
            + hv[0]*a0.x + hv[1]*a0.y + hv[2]*a0.z + hv[3]*a0.w
            + hv[4]*a1.x + hv[5]*a1.y + hv[6]*a1.z + hv[7]*a1.w
            + hv[8]*a2.x + hv[9]*a2.y + hv[10]*a2.z + hv[11]*a2.w
            + hv[12]*a3.x + hv[13]*a3.y + hv[14]*a3.z + hv[15]*a3.w;
        h = acc;
        if (lane < NS) g_hs[(size_t)(r0 + t) * NS + m] = h;
    }
}

// ---------------- kernel 4: y = hs @ C^T + D*u (float4 broadcast LDS, 2-deep u prefetch) ----------------
__global__ __launch_bounds__(256) void k_out(const float* __restrict__ u,
                                             const float* __restrict__ C,
                                             const float* __restrict__ D,
                                             float* __restrict__ y) {
    __shared__ __align__(16) float hs_s[256];
    int tid = threadIdx.x;
    int d   = blockIdx.x * 256 + tid;
    int r0  = blockIdx.y * 16;
    hs_s[tid] = g_hs[(size_t)r0 * NS + tid];
    const float4* c4 = (const float4*)(C + (size_t)d * NS);
    float4 c0 = c4[0], c1 = c4[1], c2 = c4[2], c3 = c4[3];
    float Dd = D[d];
    float ucur = u[(size_t)r0 * DIM + d];
    __syncthreads();
    #pragma unroll
    for (int sl = 0; sl < 16; sl++) {
        float unext = 0.f;
        if (sl + 1 < 16) unext = u[(size_t)(r0 + sl + 1) * DIM + d];
        const float4* hp = (const float4*)(hs_s + sl * 16);
        float4 h0 = hp[0], h1 = hp[1], h2 = hp[2], h3 = hp[3];
        float yv = Dd * ucur;
        yv += h0.x*c0.x + h0.y*c0.y + h0.z*c0.z + h0.w*c0.w
            + h1.x*c1.x + h1.y*c1.y + h1.z*c1.z + h1.w*c1.w
            + h2.x*c2.x + h2.y*c2.y + h2.z*c2.z + h2.w*c2.w
            + h3.x*c3.x + h3.y*c3.y + h3.z*c3.z + h3.w*c3.w;
        y[(size_t)(r0 + sl) * DIM + d] = yv;
        ucur = unext;
    }
}

// ---------------- launch ----------------
extern "C" void kernel_launch(void* const* d_in, const int* in_sizes, int n_in,
                              void* d_out, int out_size) {
    const float* u     = (const float*)d_in[0];
    const float* gate  = (const float*)d_in[1];
    const float* A_log = (const float*)d_in[2];
    const float* B_mat = (const float*)d_in[3];
    const float* C_mat = (const float*)d_in[4];
    const float* D     = (const float*)d_in[5];
    const float* dt_w  = (const float*)d_in[6];
    const float* dt_b  = (const float*)d_in[7];
    float* y = (float*)d_out;

    k_prepA<<<1, 256>>>(A_log);
    k_delta<<<ROWS/8, 256>>>(gate, dt_w, dt_b);
    k_bu<<<ROWS/128, 256>>>(u, B_mat);
    k_expm<<<ROWS/16, 256>>>();
    k_chunk<<<NCHUNK, 256>>>();
    k_combine<<<1, 256>>>();
    k_scan<<<NCHUNK, 32>>>();
    k_out<<<dim3(DIM/256, ROWS/16), 256>>>(u, C_mat, D, y);
}

// round 7
// speedup vs baseline: 2.6381x; 1.0555x over previous
#include <cuda_runtime.h>

#define BATCHN 8
#define SEQ    2048
#define DIM    1024
#define NS     16
#define ROWS   (BATCHN*SEQ)     // 16384
#define LCH    32               // chunk length
#define CPB    (SEQ/LCH)        // 64 chunks per batch
#define NCHUNK (BATCHN*CPB)     // 512 chunks
#define NTERMS 21               // Taylor degree 20
#define THETA  5.2f

// ---------------- scratch (static device globals; no runtime alloc) ----------------
__device__ float g_Anorm;
__device__ __align__(128) float g_Pd[NTERMS*256];              // A^k / k!
__device__ __align__(128) float g_Bu[ROWS*NS];
__device__ __align__(128) float g_AexpT[(size_t)ROWS*NS*NS];   // 16 MB, E^T per row: [r][m][n] = E[n][m]
__device__ __align__(128) float g_PT[NCHUNK*NS*NS];            // chunk product transposed
__device__ __align__(128) float g_e[NCHUNK*NS];                // chunk local end-state
__device__ __align__(128) float g_hstart[NCHUNK*NS];           // state at chunk start
__device__ __align__(128) float g_hs[(size_t)ROWS*NS];

// ---------------- f32x2 helpers ----------------
__device__ __forceinline__ unsigned long long pk2(float lo, float hi) {
    unsigned long long r;
    asm("mov.b64 %0, {%1, %2};" : "=l"(r) : "f"(lo), "f"(hi));
    return r;
}
__device__ __forceinline__ float2 upk2(unsigned long long v) {
    float2 r;
    asm("mov.b64 {%0, %1}, %2;" : "=f"(r.x), "=f"(r.y) : "l"(v));
    return r;
}
__device__ __forceinline__ void fma2(unsigned long long& d, unsigned long long a, unsigned long long b) {
    asm("fma.rn.f32x2 %0, %1, %2, %0;" : "+l"(d) : "l"(a), "l"(b));
}

// ---------------- kernel 0: A = -exp(A_log), inf-norm, P_k = A^k/k! ----------------
__global__ __launch_bounds__(256) void k_prepA(const float* __restrict__ A_log) {
    __shared__ float As[256];
    __shared__ float buf[2][256];
    __shared__ float rowsum[NS];
    int tid = threadIdx.x;
    int i = tid >> 4, j = tid & 15;
    float a = -expf(A_log[tid]);
    As[tid] = a;
    __syncthreads();
    float Ac[16];                      // column j of A in registers
    #pragma unroll
    for (int k = 0; k < 16; k++) Ac[k] = As[k*16 + j];
    if (tid < NS) {
        float s = 0.f;
        #pragma unroll
        for (int c = 0; c < NS; c++) s += fabsf(As[tid*16 + c]);
        rowsum[tid] = s;
    }
    __syncthreads();
    if (tid == 0) {
        float m = 0.f;
        #pragma unroll
        for (int r = 0; r < NS; r++) m = fmaxf(m, rowsum[r]);
        g_Anorm = m;
    }
    float id = (i == j) ? 1.f : 0.f;
    buf[0][tid] = id;
    g_Pd[tid] = id;
    __syncthreads();
    int cur = 0;
    for (int k = 1; k < NTERMS; k++) {
        const float* row = &buf[cur][i*16];
        float a0 = fmaf(row[0], Ac[0], fmaf(row[1], Ac[1], fmaf(row[2], Ac[2], row[3]*Ac[3])));
        float a1 = fmaf(row[4], Ac[4], fmaf(row[5], Ac[5], fmaf(row[6], Ac[6], row[7]*Ac[7])));
        float a2 = fmaf(row[8], Ac[8], fmaf(row[9], Ac[9], fmaf(row[10], Ac[10], row[11]*Ac[11])));
        float a3 = fmaf(row[12], Ac[12], fmaf(row[13], Ac[13], fmaf(row[14], Ac[14], row[15]*Ac[15])));
        float acc = ((a0 + a1) + (a2 + a3)) * (1.f / (float)k);
        buf[cur ^ 1][tid] = acc;
        g_Pd[k*256 + tid] = acc;
        cur ^= 1;
        __syncthreads();
    }
}

// ---------------- kernel 1b: Bu = u @ B_mat, register-tiled + f32x2 ----------------
__global__ __launch_bounds__(256, 1) void k_bu(const float* __restrict__ u,
                                               const float* __restrict__ B) {
    __shared__ __align__(16) float usb[128*33];     // [row][k] pad 33
    __shared__ __align__(16) float Bst[16*34];      // [n][k]  pad 34
    int tid  = threadIdx.x;
    int ks   = tid >> 7;              // k-split half
    int ngrp = (tid >> 6) & 1;        // n group (8 each)
    int rowp = tid & 63;              // row pair
    int r0   = blockIdx.x * 128;

    unsigned long long a0[8], a1[8];
    #pragma unroll
    for (int nn = 0; nn < 8; nn++) { a0[nn] = 0ull; a1[nn] = 0ull; }

    int lrow = tid >> 3, lq = tid & 7;            // u loader mapping
    int bkk  = tid >> 3, bnp = tid & 7;           // B loader mapping
    float4 pu[4]; float2 pb;
    #pragma unroll
    for (int it = 0; it < 4; it++)
        pu[it] = *(const float4*)&u[(size_t)(r0 + lrow + it*32) * DIM + lq*4];
    pb = *(const float2*)&B[(size_t)bkk * NS + bnp*2];

    for (int t = 0; t < 32; t++) {
        #pragma unroll
        for (int it = 0; it < 4; it++) {
            int row = lrow + it*32;
            usb[row*33 + lq*4 + 0] = pu[it].x;
            usb[row*33 + lq*4 + 1] = pu[it].y;
            usb[row*33 + lq*4 + 2] = pu[it].z;
            usb[row*33 + lq*4 + 3] = pu[it].w;
        }
        Bst[(2*bnp + 0)*34 + bkk] = pb.x;
        Bst[(2*bnp + 1)*34 + bkk] = pb.y;
        __syncthreads();
        if (t + 1 < 32) {
            int kt = (t + 1) * 32;
            #pragma unroll
            for (int it = 0; it < 4; it++)
                pu[it] = *(const float4*)&u[(size_t)(r0 + lrow + it*32) * DIM + kt + lq*4];
            pb = *(const float2*)&B[(size_t)(kt + bkk) * NS + bnp*2];
        }
        int kb = ks * 16;
        #pragma unroll
        for (int kk = 0; kk < 8; kk++) {
            int k = kb + 2*kk;
            unsigned long long ua = *(const unsigned long long*)&usb[(2*rowp)*33 + k];
            const float* ur1 = &usb[(2*rowp + 1)*33 + k];
            unsigned long long ub = pk2(ur1[0], ur1[1]);
            #pragma unroll
            for (int nn = 0; nn < 8; nn++) {
                unsigned long long bb = *(const unsigned long long*)&Bst[(8*ngrp + nn)*34 + k];
                fma2(a0[nn], ua, bb);
                fma2(a1[nn], ub, bb);
            }
        }
        __syncthreads();
    }
    float* red = usb;
    if (ks == 1) {
        int p = tid - 128;
        #pragma unroll
        for (int nn = 0; nn < 8; nn++) {
            float2 x0 = upk2(a0[nn]); float2 x1 = upk2(a1[nn]);
            red[p*16 + nn]     = x0.x + x0.y;
            red[p*16 + 8 + nn] = x1.x + x1.y;
        }
    }
    __syncthreads();
    if (ks == 0) {
        #pragma unroll
        for (int nn = 0; nn < 8; nn++) {
            float2 x0 = upk2(a0[nn]); float2 x1 = upk2(a1[nn]);
            float v0 = x0.x + x0.y + red[tid*16 + nn];
            float v1 = x1.x + x1.y + red[tid*16 + 8 + nn];
            g_Bu[(size_t)(r0 + 2*rowp)     * NS + 8*ngrp + nn] = v0;
            g_Bu[(size_t)(r0 + 2*rowp + 1) * NS + 8*ngrp + nn] = v1;
        }
    }
}

// ---------------- kernel 2: fused delta + expm ----------------
// Phase 0: warp w computes delta for rows r0+2w, r0+2w+1 (coalesced gate dot).
// Phase 1: elementwise Horner (Taylor-20 in y = delta/2^s).
// Phase 2: <=2 register/shuffle squarings (2 matrices per warp).
__global__ __launch_bounds__(256, 1) void k_expm(const float* __restrict__ gate,
                                                 const float* __restrict__ dt_w,
                                                 const float* __restrict__ dt_b) {
    __shared__ float Ts[16*257];
    __shared__ float ys[16];
    __shared__ int   ss[16];
    int tid = threadIdx.x;
    int r0 = blockIdx.x * 16;
    int wid = tid >> 5, lane = tid & 31;
    const float4* w4 = (const float4*)dt_w;
    float anorm = g_Anorm;
    float b0 = dt_b[0];
    #pragma unroll
    for (int rr = 0; rr < 2; rr++) {
        int row = r0 + 2*wid + rr;
        const float4* g4 = (const float4*)(gate + (size_t)row * DIM);
        float acc = 0.f;
        #pragma unroll
        for (int ii = 0; ii < 8; ii++) {
            float4 g = g4[lane + 32*ii];
            float4 w = w4[lane + 32*ii];
            acc += g.x*w.x + g.y*w.y + g.z*w.z + g.w*w.w;
        }
        #pragma unroll
        for (int o = 16; o; o >>= 1) acc += __shfl_xor_sync(0xffffffffu, acc, o);
        if (lane == 0) {
            float d = 1.f / (1.f + expf(-(acc + b0)));
            float nn = d * anorm;
            int s = 0;
            while (nn > THETA) { nn *= 0.5f; s++; }
            ss[2*wid + rr] = s;
            ys[2*wid + rr] = ldexpf(d, -s);
        }
    }
    float p[NTERMS];
    #pragma unroll
    for (int k = 0; k < NTERMS; k++) p[k] = g_Pd[k*256 + tid];
    __syncthreads();
    #pragma unroll
    for (int r = 0; r < 16; r++) {
        float y = ys[r];
        float acc = p[NTERMS-1];
        #pragma unroll
        for (int k = NTERMS-2; k >= 0; k--) acc = acc*y + p[k];
        Ts[r*257 + tid] = acc;
    }
    __syncthreads();
    int r = tid >> 4, j = tid & 15;
    float v[16];
    #pragma unroll
    for (int i = 0; i < 16; i++) v[i] = Ts[r*257 + i*16 + j];   // v = T[:,j] of row r
    int s = ss[r];
    int smax = max(s, __shfl_xor_sync(0xffffffffu, s, 16));
    for (int q = 0; q < smax; q++) {
        float nv[16];
        #pragma unroll
        for (int i = 0; i < 16; i++) nv[i] = 0.f;
        #pragma unroll
        for (int k = 0; k < 16; k++) {
            float w = v[k];
            #pragma unroll
            for (int i = 0; i < 16; i++)
                nv[i] += __shfl_sync(0xffffffffu, v[i], k, 16) * w;
        }
        if (q < s) {
            #pragma unroll
            for (int i = 0; i < 16; i++) v[i] = nv[i];
        }
    }
    float4* o = (float4*)(g_AexpT + (size_t)(r0 + r) * 256 + j * 16);
    o[0] = make_float4(v[0], v[1], v[2], v[3]);
    o[1] = make_float4(v[4], v[5], v[6], v[7]);
    o[2] = make_float4(v[8], v[9], v[10], v[11]);
    o[3] = make_float4(v[12], v[13], v[14], v[15]);
}

// ---------------- kernel 3a: chunk products; float4 shared, ping-pong, 4-deep prefetch ----------------
__global__ __launch_bounds__(256) void k_chunk() {
    __shared__ __align__(16) float Ps[2][16*20];
    __shared__ __align__(16) float Es[2][16*20];
    __shared__ __align__(16) float esm[2][16];
    int gc = blockIdx.x;
    int tid = threadIdx.x;
    int i = tid >> 4, j = tid & 15;
    int r0 = gc * LCH;
    Ps[0][i*20 + j] = (i == j) ? 1.f : 0.f;
    if (tid < 16) esm[0][tid] = 0.f;
    float ep[4], bup[4];
    #pragma unroll
    for (int k = 0; k < 4; k++) {
        ep[k] = g_AexpT[(size_t)(r0 + k) * 256 + tid];
        bup[k] = (i == 0) ? g_Bu[(size_t)(r0 + k) * NS + j] : 0.f;
    }
    Es[0][i*20 + j] = ep[0];
    __syncthreads();
    int cur = 0;
    #pragma unroll 4
    for (int t = 0; t < LCH; t++) {
        const float4* Pr = (const float4*)&Ps[cur][i*20];
        const float4* Ec = (const float4*)&Es[t & 1][j*20];
        float4 p0 = Pr[0], p1 = Pr[1], p2 = Pr[2], p3 = Pr[3];
        float4 e0 = Ec[0], e1 = Ec[1], e2 = Ec[2], e3 = Ec[3];
        float v0 = fmaf(p0.x, e0.x, fmaf(p0.y, e0.y, fmaf(p0.z, e0.z, p0.w*e0.w)));
        float v1 = fmaf(p1.x, e1.x, fmaf(p1.y, e1.y, fmaf(p1.z, e1.z, p1.w*e1.w)));
        float v2 = fmaf(p2.x, e2.x, fmaf(p2.y, e2.y, fmaf(p2.z, e2.z, p2.w*e2.w)));
        float v3 = fmaf(p3.x, e3.x, fmaf(p3.y, e3.y, fmaf(p3.z, e3.z, p3.w*e3.w)));
        float val = (v0 + v1) + (v2 + v3);
        float ev = 0.f;
        if (i == 0) {
            const float4* em = (const float4*)&esm[cur][0];
            float4 m0 = em[0], m1 = em[1], m2 = em[2], m3 = em[3];
            float w0 = fmaf(m0.x, e0.x, fmaf(m0.y, e0.y, fmaf(m0.z, e0.z, m0.w*e0.w)));
            float w1 = fmaf(m1.x, e1.x, fmaf(m1.y, e1.y, fmaf(m1.z, e1.z, m1.w*e1.w)));
            float w2 = fmaf(m2.x, e2.x, fmaf(m2.y, e2.y, fmaf(m2.z, e2.z, m2.w*e2.w)));
            float w3 = fmaf(m3.x, e3.x, fmaf(m3.y, e3.y, fmaf(m3.z, e3.z, m3.w*e3.w)));
            ev = bup[t & 3] + ((w0 + w1) + (w2 + w3));
        }
        if (t + 1 < LCH) Es[(t + 1) & 1][i*20 + j] = ep[(t + 1) & 3];
        if (t + 4 < LCH) {
            ep[t & 3] = g_AexpT[(size_t)(r0 + t + 4) * 256 + tid];
            if (i == 0) bup[t & 3] = g_Bu[(size_t)(r0 + t + 4) * NS + j];
        }
        Ps[cur ^ 1][i*20 + j] = val;
        if (i == 0) esm[cur ^ 1][j] = ev;
        cur ^= 1;
        __syncthreads();
    }
    g_PT[gc * 256 + tid] = Ps[cur][j*20 + i];   // PT[m][n] = P[n][m]
    if (tid < 16) g_e[gc * NS + tid] = esm[cur][tid];
}

// ---------------- kernel 3b: sequential chunk combine, warp per batch, 4-deep prefetch ----------------
__global__ __launch_bounds__(256, 1) void k_combine() {
    int tid  = threadIdx.x;
    int b    = tid >> 5;
    int lane = tid & 31;
    int m    = lane & 15;
    float h = 0.f;
    int gc0 = b * CPB;
    float4 P4[4][4]; float ee[4];
    #pragma unroll
    for (int k = 0; k < 4; k++) {
        const float4* p4 = (const float4*)(g_PT + (gc0 + k) * 256 + m * NS);
        P4[k][0] = p4[0]; P4[k][1] = p4[1]; P4[k][2] = p4[2]; P4[k][3] = p4[3];
        ee[k] = g_e[(gc0 + k) * NS + m];
    }
    #pragma unroll 4
    for (int c = 0; c < CPB; c++) {
        int sl = c & 3;
        int gc = gc0 + c;
        if (lane < NS) g_hstart[gc * NS + lane] = h;
        float4 p0 = P4[sl][0], p1 = P4[sl][1], p2 = P4[sl][2], p3 = P4[sl][3];
        float e = ee[sl];
        if (c + 4 < CPB) {
            const float4* n4 = (const float4*)(g_PT + (gc + 4) * 256 + m * NS);
            P4[sl][0] = n4[0]; P4[sl][1] = n4[1]; P4[sl][2] = n4[2]; P4[sl][3] = n4[3];
            ee[sl] = g_e[(gc + 4) * NS + m];
        }
        float hv[NS];
        #pragma unroll
        for (int n = 0; n < NS; n++) hv[n] = __shfl_sync(0xffffffffu, h, n, 32);
        float t0 = fmaf(hv[0], p0.x, fmaf(hv[1], p0.y, fmaf(hv[2], p0.z, hv[3]*p0.w)));
        float t1 = fmaf(hv[4], p1.x, fmaf(hv[5], p1.y, fmaf(hv[6], p1.z, hv[7]*p1.w)));
        float t2 = fmaf(hv[8], p2.x, fmaf(hv[9], p2.y, fmaf(hv[10], p2.z, hv[11]*p2.w)));
        float t3 = fmaf(hv[12], p3.x, fmaf(hv[13], p3.y, fmaf(hv[14], p3.z, hv[15]*p3.w)));
        h = e + ((t0 + t1) + (t2 + t3));
    }
}

// ---------------- kernel 3c: per-chunk matvec scan, 4-deep prefetch ----------------
__global__ __launch_bounds__(32) void k_scan() {
    int gc   = blockIdx.x;
    int lane = threadIdx.x & 31;
    int m    = lane & 15;
    int r0   = gc * LCH;
    float h = g_hstart[gc * NS + m];
    const float4* base = (const float4*)(g_AexpT + (size_t)r0 * 256 + m * NS);
    float4 Ea[4][4]; float bub[4];
    #pragma unroll
    for (int k = 0; k < 4; k++) {
        const float4* p = base + (size_t)k * 64;
        Ea[k][0] = p[0]; Ea[k][1] = p[1]; Ea[k][2] = p[2]; Ea[k][3] = p[3];
        bub[k] = g_Bu[(size_t)(r0 + k) * NS + m];
    }
    #pragma unroll 4
    for (int t = 0; t < LCH; t++) {
        int sl = t & 3;
        float4 a0 = Ea[sl][0], a1 = Ea[sl][1], a2 = Ea[sl][2], a3 = Ea[sl][3];
        float bu = bub[sl];
        if (t + 4 < LCH) {
            const float4* p = base + (size_t)(t + 4) * 64;
            Ea[sl][0] = p[0]; Ea[sl][1] = p[1]; Ea[sl][2] = p[2]; Ea[sl][3] = p[3];
            bub[sl] = g_Bu[(size_t)(r0 + t + 4) * NS + m];
        }
        float hv[NS];
        #pragma unroll
        for (int n = 0; n < NS; n++) hv[n] = __shfl_sync(0xffffffffu, h, n, 32);
        float t0 = fmaf(hv[0], a0.x, fmaf(hv[1], a0.y, fmaf(hv[2], a0.z, hv[3]*a0.w)));
        float t1 = fmaf(hv[4], a1.x, fmaf(hv[5], a1.y, fmaf(hv[6], a1.z, hv[7]*a1.w)));
        float t2 = fmaf(hv[8], a2.x, fmaf(hv[9], a2.y, fmaf(hv[10], a2.z, hv[11]*a2.w)));
        float t3 = fmaf(hv[12], a3.x, fmaf(hv[13], a3.y, fmaf(hv[14], a3.z, hv[15]*a3.w)));
        h = bu + ((t0 + t1) + (t2 + t3));
        if (lane < NS) g_hs[(size_t)(r0 + t) * NS + m] = h;
    }
}

// ---------------- kernel 4: y = hs @ C^T + D*u (float4 broadcast LDS, u prefetch) ----------------
__global__ __launch_bounds__(256) void k_out(const float* __restrict__ u,
                                             const float* __restrict__ C,
                                             const float* __restrict__ D,
                                             float* __restrict__ y) {
    __shared__ __align__(16) float hs_s[256];
    int tid = threadIdx.x;
    int d   = blockIdx.x * 256 + tid;
    int r0  = blockIdx.y * 16;
    hs_s[tid] = g_hs[(size_t)r0 * NS + tid];
    const float4* c4 = (const float4*)(C + (size_t)d * NS);
    float4 c0 = c4[0], c1 = c4[1], c2 = c4[2], c3 = c4[3];
    float Dd = D[d];
    float ucur = u[(size_t)r0 * DIM + d];
    __syncthreads();
    #pragma unroll
    for (int sl = 0; sl < 16; sl++) {
        float unext = 0.f;
        if (sl + 1 < 16) unext = u[(size_t)(r0 + sl + 1) * DIM + d];
        const float4* hp = (const float4*)(hs_s + sl * 16);
        float4 h0 = hp[0], h1 = hp[1], h2 = hp[2], h3 = hp[3];
        float t0 = fmaf(h0.x, c0.x, fmaf(h0.y, c0.y, fmaf(h0.z, c0.z, h0.w*c0.w)));
        float t1 = fmaf(h1.x, c1.x, fmaf(h1.y, c1.y, fmaf(h1.z, c1.z, h1.w*c1.w)));
        float t2 = fmaf(h2.x, c2.x, fmaf(h2.y, c2.y, fmaf(h2.z, c2.z, h2.w*c2.w)));
        float t3 = fmaf(h3.x, c3.x, fmaf(h3.y, c3.y, fmaf(h3.z, c3.z, h3.w*c3.w)));
        y[(size_t)(r0 + sl) * DIM + d] = Dd * ucur + ((t0 + t1) + (t2 + t3));
        ucur = unext;
    }
}

// ---------------- launch ----------------
extern "C" void kernel_launch(void* const* d_in, const int* in_sizes, int n_in,
                              void* d_out, int out_size) {
    const float* u     = (const float*)d_in[0];
    const float* gate  = (const float*)d_in[1];
    const float* A_log = (const float*)d_in[2];
    const float* B_mat = (const float*)d_in[3];
    const float* C_mat = (const float*)d_in[4];
    const float* D     = (const float*)d_in[5];
    const float* dt_w  = (const float*)d_in[6];
    const float* dt_b  = (const float*)d_in[7];
    float* y = (float*)d_out;

    k_prepA<<<1, 256>>>(A_log);
    k_bu<<<ROWS/128, 256>>>(u, B_mat);
    k_expm<<<ROWS/16, 256>>>(gate, dt_w, dt_b);
    k_chunk<<<NCHUNK, 256>>>();
    k_combine<<<1, 256>>>();
    k_scan<<<NCHUNK, 32>>>();
    k_out<<<dim3(DIM/256, ROWS/16), 256>>>(u, C_mat, D, y);
}

// round 8
// speedup vs baseline: 2.8231x; 1.0702x over previous
#include <cuda_runtime.h>

#define BATCHN 8
#define SEQ    2048
#define DIM    1024
#define NS     16
#define ROWS   (BATCHN*SEQ)     // 16384
#define LCH    32               // chunk length
#define CPB    (SEQ/LCH)        // 64 chunks per batch
#define NCHUNK (BATCHN*CPB)     // 512 chunks
#define NTERMS 21               // Taylor degree 20
#define THETA  5.2f
#define MS     260              // shared matrix slot stride (floats)

// ---------------- scratch (static device globals; no runtime alloc) ----------------
__device__ float g_Anorm;
__device__ __align__(128) float g_Pd[NTERMS*256];              // A^k / k!
__device__ __align__(128) float g_Bu[ROWS*NS];
__device__ __align__(128) float g_AexpT[(size_t)ROWS*NS*NS];   // 16 MB, E^T per row: [r][m][n] = E[n][m]
__device__ __align__(128) float g_PT[NCHUNK*NS*NS];            // chunk product transposed
__device__ __align__(128) float g_e[NCHUNK*NS];                // chunk local end-state
__device__ __align__(128) float g_hstart[NCHUNK*NS];           // state at chunk start
__device__ __align__(128) float g_hs[(size_t)ROWS*NS];

// ---------------- f32x2 helpers ----------------
__device__ __forceinline__ unsigned long long pk2(float lo, float hi) {
    unsigned long long r;
    asm("mov.b64 %0, {%1, %2};" : "=l"(r) : "f"(lo), "f"(hi));
    return r;
}
__device__ __forceinline__ float2 upk2(unsigned long long v) {
    float2 r;
    asm("mov.b64 {%0, %1}, %2;" : "=f"(r.x), "=f"(r.y) : "l"(v));
    return r;
}
__device__ __forceinline__ void fma2(unsigned long long& d, unsigned long long a, unsigned long long b) {
    asm("fma.rn.f32x2 %0, %1, %2, %0;" : "+l"(d) : "l"(a), "l"(b));
}

// ---------------- kernel 0: A = -exp(A_log), inf-norm, P_k = A^k/k! ----------------
__global__ __launch_bounds__(256) void k_prepA(const float* __restrict__ A_log) {
    __shared__ float As[256];
    __shared__ float buf[2][256];
    __shared__ float rowsum[NS];
    int tid = threadIdx.x;
    int i = tid >> 4, j = tid & 15;
    float a = -expf(A_log[tid]);
    As[tid] = a;
    __syncthreads();
    float Ac[16];                      // column j of A in registers
    #pragma unroll
    for (int k = 0; k < 16; k++) Ac[k] = As[k*16 + j];
    if (tid < NS) {
        float s = 0.f;
        #pragma unroll
        for (int c = 0; c < NS; c++) s += fabsf(As[tid*16 + c]);
        rowsum[tid] = s;
    }
    __syncthreads();
    if (tid == 0) {
        float m = 0.f;
        #pragma unroll
        for (int r = 0; r < NS; r++) m = fmaxf(m, rowsum[r]);
        g_Anorm = m;
    }
    float id = (i == j) ? 1.f : 0.f;
    buf[0][tid] = id;
    g_Pd[tid] = id;
    __syncthreads();
    int cur = 0;
    for (int k = 1; k < NTERMS; k++) {
        const float* row = &buf[cur][i*16];
        float a0 = fmaf(row[0], Ac[0], fmaf(row[1], Ac[1], fmaf(row[2], Ac[2], row[3]*Ac[3])));
        float a1 = fmaf(row[4], Ac[4], fmaf(row[5], Ac[5], fmaf(row[6], Ac[6], row[7]*Ac[7])));
        float a2 = fmaf(row[8], Ac[8], fmaf(row[9], Ac[9], fmaf(row[10], Ac[10], row[11]*Ac[11])));
        float a3 = fmaf(row[12], Ac[12], fmaf(row[13], Ac[13], fmaf(row[14], Ac[14], row[15]*Ac[15])));
        float acc = ((a0 + a1) + (a2 + a3)) * (1.f / (float)k);
        buf[cur ^ 1][tid] = acc;
        g_Pd[k*256 + tid] = acc;
        cur ^= 1;
        __syncthreads();
    }
}

// ---------------- kernel 1b: Bu = u @ B_mat, register-tiled + f32x2 ----------------
__global__ __launch_bounds__(256, 1) void k_bu(const float* __restrict__ u,
                                               const float* __restrict__ B) {
    __shared__ __align__(16) float usb[128*33];     // [row][k] pad 33
    __shared__ __align__(16) float Bst[16*34];      // [n][k]  pad 34
    int tid  = threadIdx.x;
    int ks   = tid >> 7;              // k-split half
    int ngrp = (tid >> 6) & 1;        // n group (8 each)
    int rowp = tid & 63;              // row pair
    int r0   = blockIdx.x * 128;

    unsigned long long a0[8], a1[8];
    #pragma unroll
    for (int nn = 0; nn < 8; nn++) { a0[nn] = 0ull; a1[nn] = 0ull; }

    int lrow = tid >> 3, lq = tid & 7;            // u loader mapping
    int bkk  = tid >> 3, bnp = tid & 7;           // B loader mapping
    float4 pu[4]; float2 pb;
    #pragma unroll
    for (int it = 0; it < 4; it++)
        pu[it] = *(const float4*)&u[(size_t)(r0 + lrow + it*32) * DIM + lq*4];
    pb = *(const float2*)&B[(size_t)bkk * NS + bnp*2];

    for (int t = 0; t < 32; t++) {
        #pragma unroll
        for (int it = 0; it < 4; it++) {
            int row = lrow + it*32;
            usb[row*33 + lq*4 + 0] = pu[it].x;
            usb[row*33 + lq*4 + 1] = pu[it].y;
            usb[row*33 + lq*4 + 2] = pu[it].z;
            usb[row*33 + lq*4 + 3] = pu[it].w;
        }
        Bst[(2*bnp + 0)*34 + bkk] = pb.x;
        Bst[(2*bnp + 1)*34 + bkk] = pb.y;
        __syncthreads();
        if (t + 1 < 32) {
            int kt = (t + 1) * 32;
            #pragma unroll
            for (int it = 0; it < 4; it++)
                pu[it] = *(const float4*)&u[(size_t)(r0 + lrow + it*32) * DIM + kt + lq*4];
            pb = *(const float2*)&B[(size_t)(kt + bkk) * NS + bnp*2];
        }
        int kb = ks * 16;
        #pragma unroll
        for (int kk = 0; kk < 8; kk++) {
            int k = kb + 2*kk;
            unsigned long long ua = *(const unsigned long long*)&usb[(2*rowp)*33 + k];
            const float* ur1 = &usb[(2*rowp + 1)*33 + k];
            unsigned long long ub = pk2(ur1[0], ur1[1]);
            #pragma unroll
            for (int nn = 0; nn < 8; nn++) {
                unsigned long long bb = *(const unsigned long long*)&Bst[(8*ngrp + nn)*34 + k];
                fma2(a0[nn], ua, bb);
                fma2(a1[nn], ub, bb);
            }
        }
        __syncthreads();
    }
    float* red = usb;
    if (ks == 1) {
        int p = tid - 128;
        #pragma unroll
        for (int nn = 0; nn < 8; nn++) {
            float2 x0 = upk2(a0[nn]); float2 x1 = upk2(a1[nn]);
            red[p*16 + nn]     = x0.x + x0.y;
            red[p*16 + 8 + nn] = x1.x + x1.y;
        }
    }
    __syncthreads();
    if (ks == 0) {
        #pragma unroll
        for (int nn = 0; nn < 8; nn++) {
            float2 x0 = upk2(a0[nn]); float2 x1 = upk2(a1[nn]);
            float v0 = x0.x + x0.y + red[tid*16 + nn];
            float v1 = x1.x + x1.y + red[tid*16 + 8 + nn];
            g_Bu[(size_t)(r0 + 2*rowp)     * NS + 8*ngrp + nn] = v0;
            g_Bu[(size_t)(r0 + 2*rowp + 1) * NS + 8*ngrp + nn] = v1;
        }
    }
}

// ---------------- kernel 2: fused delta + expm ----------------
__global__ __launch_bounds__(256, 1) void k_expm(const float* __restrict__ gate,
                                                 const float* __restrict__ dt_w,
                                                 const float* __restrict__ dt_b) {
    __shared__ float Ts[16*257];
    __shared__ float ys[16];
    __shared__ int   ss[16];
    int tid = threadIdx.x;
    int r0 = blockIdx.x * 16;
    int wid = tid >> 5, lane = tid & 31;
    const float4* w4 = (const float4*)dt_w;
    float anorm = g_Anorm;
    float b0 = dt_b[0];
    #pragma unroll
    for (int rr = 0; rr < 2; rr++) {
        int row = r0 + 2*wid + rr;
        const float4* g4 = (const float4*)(gate + (size_t)row * DIM);
        float acc = 0.f;
        #pragma unroll
        for (int ii = 0; ii < 8; ii++) {
            float4 g = g4[lane + 32*ii];
            float4 w = w4[lane + 32*ii];
            acc += g.x*w.x + g.y*w.y + g.z*w.z + g.w*w.w;
        }
        #pragma unroll
        for (int o = 16; o; o >>= 1) acc += __shfl_xor_sync(0xffffffffu, acc, o);
        if (lane == 0) {
            float d = 1.f / (1.f + expf(-(acc + b0)));
            float nn = d * anorm;
            int s = 0;
            while (nn > THETA) { nn *= 0.5f; s++; }
            ss[2*wid + rr] = s;
            ys[2*wid + rr] = ldexpf(d, -s);
        }
    }
    float p[NTERMS];
    #pragma unroll
    for (int k = 0; k < NTERMS; k++) p[k] = g_Pd[k*256 + tid];
    __syncthreads();
    #pragma unroll
    for (int r = 0; r < 16; r++) {
        float y = ys[r];
        float acc = p[NTERMS-1];
        #pragma unroll
        for (int k = NTERMS-2; k >= 0; k--) acc = acc*y + p[k];
        Ts[r*257 + tid] = acc;
    }
    __syncthreads();
    int r = tid >> 4, j = tid & 15;
    float v[16];
    #pragma unroll
    for (int i = 0; i < 16; i++) v[i] = Ts[r*257 + i*16 + j];   // v = T[:,j] of row r
    int s = ss[r];
    int smax = max(s, __shfl_xor_sync(0xffffffffu, s, 16));
    for (int q = 0; q < smax; q++) {
        float nv[16];
        #pragma unroll
        for (int i = 0; i < 16; i++) nv[i] = 0.f;
        #pragma unroll
        for (int k = 0; k < 16; k++) {
            float w = v[k];
            #pragma unroll
            for (int i = 0; i < 16; i++)
                nv[i] += __shfl_sync(0xffffffffu, v[i], k, 16) * w;
        }
        if (q < s) {
            #pragma unroll
            for (int i = 0; i < 16; i++) v[i] = nv[i];
        }
    }
    float4* o = (float4*)(g_AexpT + (size_t)(r0 + r) * 256 + j * 16);
    o[0] = make_float4(v[0], v[1], v[2], v[3]);
    o[1] = make_float4(v[4], v[5], v[6], v[7]);
    o[2] = make_float4(v[8], v[9], v[10], v[11]);
    o[3] = make_float4(v[12], v[13], v[14], v[15]);
}

// ---------------- kernel 3a: chunk products via BALANCED TREE ----------------
// Transposed storage S = P^T. Combine of left-then-right segment:
//   S_out = S_R @ S_L,  e_out[i] = dot(S_R row i, e_L) + e_R[i].
// Regions: X = slots 0..15, Y = slots 16..31 (ping-pong). ~35.5 KB shared.
__device__ __forceinline__ void tree_combine(float* Em, float* es,
                                             int sL, int sR, int sO, int i) {
    const float* A = &Em[sR*MS + i*16];     // row i of right child
    const float* B = &Em[sL*MS];            // full left child
    float a[16];
    #pragma unroll
    for (int k = 0; k < 16; k++) a[k] = A[k];
    float4 c0 = make_float4(0,0,0,0), c1 = c0, c2 = c0, c3 = c0;
    #pragma unroll
    for (int k = 0; k < 16; k++) {
        const float4* bk = (const float4*)(B + k*16);
        float4 b0 = bk[0], b1 = bk[1], b2 = bk[2], b3 = bk[3];
        float w = a[k];
        c0.x = fmaf(w, b0.x, c0.x); c0.y = fmaf(w, b0.y, c0.y);
        c0.z = fmaf(w, b0.z, c0.z); c0.w = fmaf(w, b0.w, c0.w);
        c1.x = fmaf(w, b1.x, c1.x); c1.y = fmaf(w, b1.y, c1.y);
        c1.z = fmaf(w, b1.z, c1.z); c1.w = fmaf(w, b1.w, c1.w);
        c2.x = fmaf(w, b2.x, c2.x); c2.y = fmaf(w, b2.y, c2.y);
        c2.z = fmaf(w, b2.z, c2.z); c2.w = fmaf(w, b2.w, c2.w);
        c3.x = fmaf(w, b3.x, c3.x); c3.y = fmaf(w, b3.y, c3.y);
        c3.z = fmaf(w, b3.z, c3.z); c3.w = fmaf(w, b3.w, c3.w);
    }
    const float* eL = &es[sL*17];
    float ev = es[sR*17 + i];
    #pragma unroll
    for (int k = 0; k < 16; k++) ev = fmaf(a[k], eL[k], ev);
    float4* C4 = (float4*)&Em[sO*MS + i*16];
    C4[0] = c0; C4[1] = c1; C4[2] = c2; C4[3] = c3;
    es[sO*17 + i] = ev;
}

__global__ __launch_bounds__(256) void k_chunk() {
    __shared__ __align__(16) float Em[32*MS];
    __shared__ float es[32*17];
    int gc = blockIdx.x, tid = threadIdx.x;
    int r0 = gc * LCH;
    int q = tid >> 4, i = tid & 15;
    // ---- stage A: leaves 0..15 into X ----
    #pragma unroll
    for (int t = 0; t < 16; t++)
        Em[t*MS + tid] = g_AexpT[(size_t)(r0 + t) * 256 + tid];
    if (tid < 256) {
        for (int idx = tid; idx < 16*16; idx += 256)
            es[(idx >> 4)*17 + (idx & 15)] = g_Bu[(size_t)r0 * NS + idx];
    }
    __syncthreads();
    if (tid < 128) tree_combine(Em, es, 2*q, 2*q + 1, 16 + q, i);     // L1[0..7] -> Y 16..23
    __syncthreads();
    // ---- stage B: leaves 16..31 into X ----
    #pragma unroll
    for (int t = 0; t < 16; t++)
        Em[t*MS + tid] = g_AexpT[(size_t)(r0 + 16 + t) * 256 + tid];
    for (int idx = tid; idx < 16*16; idx += 256)
        es[(idx >> 4)*17 + (idx & 15)] = g_Bu[(size_t)(r0 + 16) * NS + idx];
    __syncthreads();
    if (tid < 128) tree_combine(Em, es, 2*q, 2*q + 1, 24 + q, i);     // L1[8..15] -> Y 24..31
    __syncthreads();
    // ---- level 2: Y[16..31] -> X[0..7] ----
    if (tid < 128) tree_combine(Em, es, 16 + 2*q, 16 + 2*q + 1, q, i);
    __syncthreads();
    // ---- level 3: X[0..7] -> Y[16..19] ----
    if (tid < 64)  tree_combine(Em, es, 2*q, 2*q + 1, 16 + q, i);
    __syncthreads();
    // ---- level 4: Y[16..19] -> X[0..1] ----
    if (tid < 32)  tree_combine(Em, es, 16 + 2*q, 16 + 2*q + 1, q, i);
    __syncthreads();
    // ---- level 5: X[0..1] -> Y[16] ----
    if (tid < 16)  tree_combine(Em, es, 0, 1, 16, i);
    __syncthreads();
    g_PT[gc * 256 + tid] = Em[16*MS + tid];
    if (tid < 16) g_e[gc * NS + tid] = es[16*17 + tid];
}

// ---------------- kernel 3b: sequential chunk combine, warp per batch, 4-deep prefetch ----------------
__global__ __launch_bounds__(256, 1) void k_combine() {
    int tid  = threadIdx.x;
    int b    = tid >> 5;
    int lane = tid & 31;
    int m    = lane & 15;
    float h = 0.f;
    int gc0 = b * CPB;
    float4 P4[4][4]; float ee[4];
    #pragma unroll
    for (int k = 0; k < 4; k++) {
        const float4* p4 = (const float4*)(g_PT + (gc0 + k) * 256 + m * NS);
        P4[k][0] = p4[0]; P4[k][1] = p4[1]; P4[k][2] = p4[2]; P4[k][3] = p4[3];
        ee[k] = g_e[(gc0 + k) * NS + m];
    }
    #pragma unroll 4
    for (int c = 0; c < CPB; c++) {
        int sl = c & 3;
        int gc = gc0 + c;
        if (lane < NS) g_hstart[gc * NS + lane] = h;
        float4 p0 = P4[sl][0], p1 = P4[sl][1], p2 = P4[sl][2], p3 = P4[sl][3];
        float e = ee[sl];
        if (c + 4 < CPB) {
            const float4* n4 = (const float4*)(g_PT + (gc + 4) * 256 + m * NS);
            P4[sl][0] = n4[0]; P4[sl][1] = n4[1]; P4[sl][2] = n4[2]; P4[sl][3] = n4[3];
            ee[sl] = g_e[(gc + 4) * NS + m];
        }
        float hv[NS];
        #pragma unroll
        for (int n = 0; n < NS; n++) hv[n] = __shfl_sync(0xffffffffu, h, n, 32);
        float t0 = fmaf(hv[0], p0.x, fmaf(hv[1], p0.y, fmaf(hv[2], p0.z, hv[3]*p0.w)));
        float t1 = fmaf(hv[4], p1.x, fmaf(hv[5], p1.y, fmaf(hv[6], p1.z, hv[7]*p1.w)));
        float t2 = fmaf(hv[8], p2.x, fmaf(hv[9], p2.y, fmaf(hv[10], p2.z, hv[11]*p2.w)));
        float t3 = fmaf(hv[12], p3.x, fmaf(hv[13], p3.y, fmaf(hv[14], p3.z, hv[15]*p3.w)));
        h = e + ((t0 + t1) + (t2 + t3));
    }
}

// ---------------- kernel 3c: per-chunk matvec scan, 4-deep prefetch ----------------
__global__ __launch_bounds__(32) void k_scan() {
    int gc   = blockIdx.x;
    int lane = threadIdx.x & 31;
    int m    = lane & 15;
    int r0   = gc * LCH;
    float h = g_hstart[gc * NS + m];
    const float4* base = (const float4*)(g_AexpT + (size_t)r0 * 256 + m * NS);
    float4 Ea[4][4]; float bub[4];
    #pragma unroll
    for (int k = 0; k < 4; k++) {
        const float4* p = base + (size_t)k * 64;
        Ea[k][0] = p[0]; Ea[k][1] = p[1]; Ea[k][2] = p[2]; Ea[k][3] = p[3];
        bub[k] = g_Bu[(size_t)(r0 + k) * NS + m];
    }
    #pragma unroll 4
    for (int t = 0; t < LCH; t++) {
        int sl = t & 3;
        float4 a0 = Ea[sl][0], a1 = Ea[sl][1], a2 = Ea[sl][2], a3 = Ea[sl][3];
        float bu = bub[sl];
        if (t + 4 < LCH) {
            const float4* p = base + (size_t)(t + 4) * 64;
            Ea[sl][0] = p[0]; Ea[sl][1] = p[1]; Ea[sl][2] = p[2]; Ea[sl][3] = p[3];
            bub[sl] = g_Bu[(size_t)(r0 + t + 4) * NS + m];
        }
        float hv[NS];
        #pragma unroll
        for (int n = 0; n < NS; n++) hv[n] = __shfl_sync(0xffffffffu, h, n, 32);
        float t0 = fmaf(hv[0], a0.x, fmaf(hv[1], a0.y, fmaf(hv[2], a0.z, hv[3]*a0.w)));
        float t1 = fmaf(hv[4], a1.x, fmaf(hv[5], a1.y, fmaf(hv[6], a1.z, hv[7]*a1.w)));
        float t2 = fmaf(hv[8], a2.x, fmaf(hv[9], a2.y, fmaf(hv[10], a2.z, hv[11]*a2.w)));
        float t3 = fmaf(hv[12], a3.x, fmaf(hv[13], a3.y, fmaf(hv[14], a3.z, hv[15]*a3.w)));
        h = bu + ((t0 + t1) + (t2 + t3));
        if (lane < NS) g_hs[(size_t)(r0 + t) * NS + m] = h;
    }
}

// ---------------- kernel 4: y = hs @ C^T + D*u (32 rows/block, float4 broadcast LDS) ----------------
__global__ __launch_bounds__(256) void k_out(const float* __restrict__ u,
                                             const float* __restrict__ C,
                                             const float* __restrict__ D,
                                             float* __restrict__ y) {
    __shared__ __align__(16) float hs_s[512];
    int tid = threadIdx.x;
    int d   = blockIdx.x * 256 + tid;
    int r0  = blockIdx.y * 32;
    hs_s[tid]       = g_hs[(size_t)r0 * NS + tid];
    hs_s[tid + 256] = g_hs[(size_t)r0 * NS + tid + 256];
    const float4* c4 = (const float4*)(C + (size_t)d * NS);
    float4 c0 = c4[0], c1 = c4[1], c2 = c4[2], c3 = c4[3];
    float Dd = D[d];
    float ucur = u[(size_t)r0 * DIM + d];
    __syncthreads();
    #pragma unroll 8
    for (int sl = 0; sl < 32; sl++) {
        float unext = 0.f;
        if (sl + 1 < 32) unext = u[(size_t)(r0 + sl + 1) * DIM + d];
        const float4* hp = (const float4*)(hs_s + sl * 16);
        float4 h0 = hp[0], h1 = hp[1], h2 = hp[2], h3 = hp[3];
        float t0 = fmaf(h0.x, c0.x, fmaf(h0.y, c0.y, fmaf(h0.z, c0.z, h0.w*c0.w)));
        float t1 = fmaf(h1.x, c1.x, fmaf(h1.y, c1.y, fmaf(h1.z, c1.z, h1.w*c1.w)));
        float t2 = fmaf(h2.x, c2.x, fmaf(h2.y, c2.y, fmaf(h2.z, c2.z, h2.w*c2.w)));
        float t3 = fmaf(h3.x, c3.x, fmaf(h3.y, c3.y, fmaf(h3.z, c3.z, h3.w*c3.w)));
        y[(size_t)(r0 + sl) * DIM + d] = Dd * ucur + ((t0 + t1) + (t2 + t3));
        ucur = unext;
    }
}

// ---------------- launch ----------------
extern "C" void kernel_launch(void* const* d_in, const int* in_sizes, int n_in,
                              void* d_out, int out_size) {
    const float* u     = (const float*)d_in[0];
    const float* gate  = (const float*)d_in[1];
    const float* A_log = (const float*)d_in[2];
    const float* B_mat = (const float*)d_in[3];
    const float* C_mat = (const float*)d_in[4];
    const float* D     = (const float*)d_in[5];
    const float* dt_w  = (const float*)d_in[6];
    const float* dt_b  = (const float*)d_in[7];
    float* y = (float*)d_out;

    k_prepA<<<1, 256>>>(A_log);
    k_bu<<<ROWS/128, 256>>>(u, B_mat);
    k_expm<<<ROWS/16, 256>>>(gate, dt_w, dt_b);
    k_chunk<<<NCHUNK, 256>>>();
    k_combine<<<1, 256>>>();
    k_scan<<<NCHUNK, 32>>>();
    k_out<<<dim3(DIM/256, ROWS/32), 256>>>(u, C_mat, D, y);
}